// round 2
// baseline (speedup 1.0000x reference)
#include <cuda_runtime.h>
#include <math.h>

// ---------------- static shapes ----------------
// B=8, HID=256, ZC=64, K=512
// x: (8,3,128,128)  h1: (8,256,64,64)  h2/r/d0: (8,256,32,32)
// ze/ek: (8,64,32,32)  d1: (8,256,64,64)  out: (8,3,128,128)

// ---------------- device scratch ----------------
__device__ float g_h1[8*256*64*64];
__device__ float g_h2[8*256*32*32];
__device__ float g_r [8*256*32*32];
__device__ float g_ze[8*64*32*32];
__device__ float g_ek[8*64*32*32];
__device__ float g_d0[8*256*32*32];
__device__ float g_d1[8*256*64*64];
__device__ int   g_ids[8192];
__device__ float g_cbn[512];
// pre-transposed weights [K][Cout]
__device__ float g_wc1 [48*256];
__device__ float g_wc2 [4096*256];
__device__ float g_wr03[2304*256];
__device__ float g_wr01[256*256];
__device__ float g_wr13[2304*256];
__device__ float g_wr11[256*256];
__device__ float g_wtoz[256*64];
__device__ float g_wfz [64*256];
__device__ float g_wt1 [4*1024*256];

// ---------------- weight prep ----------------
__global__ void wtrans(const float* __restrict__ src, float* __restrict__ dst,
                       int Cout, int K) {
    int i = blockIdx.x * 256 + threadIdx.x;
    if (i >= Cout * K) return;
    int k = i / Cout, oc = i - k * Cout;
    dst[i] = src[(size_t)oc * K + k];   // OIHW flat: w[oc][k] -> wT[k][oc]
}

// t1 (ConvTranspose2d weights: (in=256, out=256, 4, 4)) -> per-parity-class [k=ic*4+a*2+b][oc]
__global__ void t1trans(const float* __restrict__ w, float* __restrict__ dst) {
    int i = blockIdx.x * 256 + threadIdx.x;
    if (i >= 4 * 1024 * 256) return;
    int cls = i >> 18;
    int r   = i & 262143;
    int k = r >> 8, oc = r & 255;
    int ic = k >> 2, t = k & 3;
    int a = t >> 1, bb = t & 1;
    int ry = cls >> 1, rx = cls & 1;
    int ky = ry ? (a ? 2 : 0) : (a ? 3 : 1);
    int kx = rx ? (bb ? 2 : 0) : (bb ? 3 : 1);
    dst[i] = w[((size_t)(ic * 256 + oc)) * 16 + ky * 4 + kx];
}

__global__ void cbnorm_k(const float* __restrict__ cb) {
    int k = blockIdx.x * 64 + threadIdx.x;
    if (k >= 512) return;
    const float* r = cb + (size_t)k * 64;
    float s0 = 0, s1 = 0, s2 = 0, s3 = 0;
#pragma unroll
    for (int c = 0; c < 64; c += 4) {
        s0 += r[c] * r[c]; s1 += r[c+1] * r[c+1];
        s2 += r[c+2] * r[c+2]; s3 += r[c+3] * r[c+3];
    }
    g_cbn[k] = (s0 + s1) + (s2 + s3);
}

// ---------------- implicit-GEMM conv ----------------
#define FMA16 \
    acc[0][0] += bv.x*a.x; acc[0][1] += bv.x*a.y; acc[0][2] += bv.x*a.z; acc[0][3] += bv.x*a.w; \
    acc[1][0] += bv.y*a.x; acc[1][1] += bv.y*a.y; acc[1][2] += bv.y*a.z; acc[1][3] += bv.y*a.w; \
    acc[2][0] += bv.z*a.x; acc[2][1] += bv.z*a.y; acc[2][2] += bv.z*a.z; acc[2][3] += bv.z*a.w; \
    acc[3][0] += bv.w*a.x; acc[3][1] += bv.w*a.y; acc[3][2] += bv.w*a.z; acc[3][3] += bv.w*a.w;

// C[m=spatial][n=out_ch] = im2col(in) @ wT ; BM=BN=64, BK=16, 256 thr, 4x4 microtile
template<int KH, int KW, int STR, int PAD, int OW, int RIN, int ROUT, int ADDRES>
__global__ __launch_bounds__(256) void conv_k(
    const float* __restrict__ in, const float* __restrict__ wT,
    const float* __restrict__ bias, const float* __restrict__ res,
    float* __restrict__ out, int Cin, int IH, int IW, int MIMG, int Cout)
{
    constexpr int T = KH * KW;
    const int K  = Cin * T;
    const int b  = blockIdx.z;
    const int m0 = blockIdx.x * 64;
    const int n0 = blockIdx.y * 64;
    __shared__ float As[16][64];
    __shared__ float Bs[16][64];
    const int tid = threadIdx.x;
    const int lm = tid & 63, lk = tid >> 6;
    const int mi = (tid & 15) << 2, ni = (tid >> 4) << 2;

    const int am = m0 + lm;
    const int ay = am / OW, ax = am % OW;          // OW is compile-time pow2
    const int ybase = ay * STR - PAD, xbase = ax * STR - PAD;
    const float* inb = in + (size_t)b * Cin * IH * IW;

    float acc[4][4] = {};
    for (int k0 = 0; k0 < K; k0 += 16) {
#pragma unroll
        for (int i = 0; i < 4; i++) {
            int k   = k0 + lk + i * 4;
            int ic  = k / T;
            int tap = k - ic * T;
            int ky  = tap / KW;
            int kx  = tap - ky * KW;
            int iy = ybase + ky, ix = xbase + kx;
            float v = 0.f;
            if ((unsigned)iy < (unsigned)IH && (unsigned)ix < (unsigned)IW)
                v = inb[(size_t)ic * IH * IW + iy * IW + ix];
            if (RIN) v = fmaxf(v, 0.f);
            As[lk + i * 4][lm] = v;
            Bs[lk + i * 4][lm] = wT[(size_t)k * Cout + n0 + lm];
        }
        __syncthreads();
#pragma unroll
        for (int kk = 0; kk < 16; kk++) {
            float4 a  = *(const float4*)&As[kk][mi];
            float4 bv = *(const float4*)&Bs[kk][ni];
            FMA16
        }
        __syncthreads();
    }
    const int m = m0 + mi;
#pragma unroll
    for (int i = 0; i < 4; i++) {
        int oc = n0 + ni + i;
        size_t ob = ((size_t)b * Cout + oc) * MIMG + m;
        float bb = bias[oc];
        float4 r;
        r.x = acc[i][0] + bb; r.y = acc[i][1] + bb;
        r.z = acc[i][2] + bb; r.w = acc[i][3] + bb;
        if (ADDRES) {
            float4 rv = *(const float4*)&res[ob];
            r.x += rv.x; r.y += rv.y; r.z += rv.z; r.w += rv.w;
        }
        if (ROUT) {
            r.x = fmaxf(r.x, 0.f); r.y = fmaxf(r.y, 0.f);
            r.z = fmaxf(r.z, 0.f); r.w = fmaxf(r.w, 0.f);
        }
        *(float4*)&out[ob] = r;
    }
}

// ---------------- transposed conv t1 (256->256, 32x32 -> 64x64), parity-class GEMM ----------------
__global__ __launch_bounds__(256) void convt1_k(
    const float* __restrict__ in, const float* __restrict__ wT,
    const float* __restrict__ bias, float* __restrict__ out)
{
    const int zc = blockIdx.z;
    const int b = zc >> 2, cls = zc & 3;
    const int ry = cls >> 1, rx = cls & 1;
    const int oy0 = ry ? 1 : 0, oy1 = ry ? 0 : -1;
    const int ox0 = rx ? 1 : 0, ox1 = rx ? 0 : -1;
    const int m0 = blockIdx.x * 64, n0 = blockIdx.y * 64;
    __shared__ float As[16][64];
    __shared__ float Bs[16][64];
    const int tid = threadIdx.x;
    const int lm = tid & 63, lk = tid >> 6;
    const int mi = (tid & 15) << 2, ni = (tid >> 4) << 2;
    const int am = m0 + lm;
    const int ay = am >> 5, ax = am & 31;
    const float* inb = in + (size_t)b * 256 * 1024;
    const float* wc  = wT + (size_t)cls * 1024 * 256;

    float acc[4][4] = {};
    for (int k0 = 0; k0 < 1024; k0 += 16) {
#pragma unroll
        for (int i = 0; i < 4; i++) {
            int k = k0 + lk + i * 4;
            int ic = k >> 2, t = k & 3;
            int iy = ay + ((t & 2) ? oy1 : oy0);
            int ix = ax + ((t & 1) ? ox1 : ox0);
            float v = 0.f;
            if ((unsigned)iy < 32u && (unsigned)ix < 32u)
                v = inb[ic * 1024 + iy * 32 + ix];
            As[lk + i * 4][lm] = v;
            Bs[lk + i * 4][lm] = wc[(size_t)k * 256 + n0 + lm];
        }
        __syncthreads();
#pragma unroll
        for (int kk = 0; kk < 16; kk++) {
            float4 a  = *(const float4*)&As[kk][mi];
            float4 bv = *(const float4*)&Bs[kk][ni];
            FMA16
        }
        __syncthreads();
    }
    const int mbase = m0 + mi;
#pragma unroll
    for (int i = 0; i < 4; i++) {
        int oc = n0 + ni + i;
        float bb = bias[oc];
#pragma unroll
        for (int j = 0; j < 4; j++) {
            int m = mbase + j;
            int y = m >> 5, x = m & 31;
            int oy = 2 * y + ry, ox = 2 * x + rx;
            float v = fmaxf(acc[i][j] + bb, 0.f);
            out[((size_t)(b * 256 + oc) * 64 + oy) * 64 + ox] = v;
        }
    }
}

// ---------------- t2 (256 -> 3, 64x64 -> 128x128) + sigmoid ----------------
__global__ __launch_bounds__(256) void t2_k(const float* __restrict__ w,
                                            const float* __restrict__ bias,
                                            float* __restrict__ out)
{
    const int cls = blockIdx.z, b = blockIdx.y;
    const int ry = cls >> 1, rx = cls & 1;
    const int oy0 = ry ? 1 : 0, oy1 = ry ? 0 : -1;
    const int ox1 = rx ? 0 : -1;
    __shared__ float ws[3072];       // [ic][t=a*2+bb][oc]
    for (int i = threadIdx.x; i < 3072; i += 256) {
        int ic = i / 12, r = i - ic * 12;
        int t = r / 3, oc = r - t * 3;
        int a = t >> 1, bb = t & 1;
        int ky = ry ? (a ? 2 : 0) : (a ? 3 : 1);
        int kx = rx ? (bb ? 2 : 0) : (bb ? 3 : 1);
        ws[i] = w[((size_t)(ic * 3 + oc)) * 16 + ky * 4 + kx];
    }
    __syncthreads();
    const int t = blockIdx.x * 256 + threadIdx.x;   // 0..1023
    const int yy = t >> 4;
    const int xg = (t & 15) << 2;
    const int basex = xg + ox1;
    const float* inb = g_d1 + (size_t)b * 256 * 4096;
    float acc[4][3] = {};
    for (int ic = 0; ic < 256; ic++) {
        const float* ip = inb + ic * 4096;
        float v[2][5];
#pragma unroll
        for (int a = 0; a < 2; a++) {
            int iy = yy + (a ? oy1 : oy0);
            bool okr = (unsigned)iy < 64u;
#pragma unroll
            for (int q = 0; q < 5; q++) {
                int ix = basex + q;
                v[a][q] = (okr && (unsigned)ix < 64u) ? ip[iy * 64 + ix] : 0.f;
            }
        }
        const float* wr = &ws[ic * 12];
#pragma unroll
        for (int p = 0; p < 4; p++)
#pragma unroll
            for (int bb2 = 0; bb2 < 2; bb2++) {
#pragma unroll
                for (int a = 0; a < 2; a++) {
                    float val = v[a][p + (bb2 ? 0 : 1)];
                    int ti = a * 2 + bb2;
                    acc[p][0] += val * wr[ti * 3 + 0];
                    acc[p][1] += val * wr[ti * 3 + 1];
                    acc[p][2] += val * wr[ti * 3 + 2];
                }
            }
    }
#pragma unroll
    for (int p = 0; p < 4; p++) {
        int oy = 2 * yy + ry, ox = 2 * (xg + p) + rx;
#pragma unroll
        for (int oc = 0; oc < 3; oc++) {
            float vv = acc[p][oc] + bias[oc];
            out[((size_t)(b * 3 + oc) * 128 + oy) * 128 + ox] = 1.f / (1.f + __expf(-vv));
        }
    }
}

// ---------------- VQ: argmin over 512 codes, gather e_k ----------------
__global__ __launch_bounds__(256) void vq_k(const float* __restrict__ cb)
{
    const int n = blockIdx.x * 256 + threadIdx.x;      // 8192 positions
    const int b = n >> 10, s = n & 1023;
    const float* zp = g_ze + (size_t)b * 64 * 1024 + s;
    float z[64];
#pragma unroll
    for (int c = 0; c < 64; c++) z[c] = zp[(size_t)c * 1024];
    float z0 = 0, z1 = 0, z2a = 0, z3 = 0;
#pragma unroll
    for (int c = 0; c < 64; c += 4) {
        z0 += z[c] * z[c]; z1 += z[c+1] * z[c+1];
        z2a += z[c+2] * z[c+2]; z3 += z[c+3] * z[c+3];
    }
    const float zn = (z0 + z1) + (z2a + z3);
    __shared__ float cbs[4096];
    float best = 3.4e38f; int bid = 0;
    for (int c0 = 0; c0 < 512; c0 += 64) {
        __syncthreads();
#pragma unroll
        for (int i = 0; i < 16; i++)
            cbs[threadIdx.x + i * 256] = cb[(size_t)c0 * 64 + threadIdx.x + i * 256];
        __syncthreads();
        for (int k = 0; k < 64; k++) {
            const float* cr = &cbs[k * 64];
            float d0 = 0, d1 = 0, d2 = 0, d3 = 0;
#pragma unroll
            for (int c = 0; c < 64; c += 4) {
                d0 += z[c] * cr[c];     d1 += z[c+1] * cr[c+1];
                d2 += z[c+2] * cr[c+2]; d3 += z[c+3] * cr[c+3];
            }
            float dot = (d0 + d1) + (d2 + d3);
            float score = (zn - 2.0f * dot) + g_cbn[c0 + k];
            if (score < best) { best = score; bid = c0 + k; }
        }
    }
    g_ids[n] = bid;
    const float* code = cb + (size_t)bid * 64;
    float* ep = g_ek + (size_t)b * 64 * 1024 + s;
#pragma unroll
    for (int c = 0; c < 64; c++) ep[(size_t)c * 1024] = code[c];
}

// ---------------- pack tuple tail (z_e, e_k, ids) ----------------
__global__ void pack_k(float* __restrict__ out, int out_size)
{
    int i = blockIdx.x * 256 + threadIdx.x;
    if (i < 524288) {
        int o = 393216 + i;
        if (o < out_size) out[o] = g_ze[i];
    } else if (i < 1048576) {
        int j = i - 524288;
        int o = 917504 + j;
        if (o < out_size) out[o] = g_ek[j];
    } else if (i < 1056768) {
        int j = i - 1048576;
        int o = 1441792 + j;
        if (o < out_size) out[o] = (float)g_ids[j];
    }
}

// ---------------- launch ----------------
extern "C" void kernel_launch(void* const* d_in, const int* in_sizes, int n_in,
                              void* d_out, int out_size)
{
    const float* x     = (const float*)d_in[0];
    const float* c1_w  = (const float*)d_in[1];
    const float* c1_b  = (const float*)d_in[2];
    const float* c2_w  = (const float*)d_in[3];
    const float* c2_b  = (const float*)d_in[4];
    const float* r0_w3 = (const float*)d_in[5];
    const float* r0_b3 = (const float*)d_in[6];
    const float* r0_w1 = (const float*)d_in[7];
    const float* r0_b1 = (const float*)d_in[8];
    const float* r1_w3 = (const float*)d_in[9];
    const float* r1_b3 = (const float*)d_in[10];
    const float* r1_w1 = (const float*)d_in[11];
    const float* r1_b1 = (const float*)d_in[12];
    const float* toz_w = (const float*)d_in[13];
    const float* toz_b = (const float*)d_in[14];
    const float* cb    = (const float*)d_in[15];
    const float* fz_w  = (const float*)d_in[16];
    const float* fz_b  = (const float*)d_in[17];
    const float* t1_w  = (const float*)d_in[18];
    const float* t1_b  = (const float*)d_in[19];
    const float* t2_w  = (const float*)d_in[20];
    const float* t2_b  = (const float*)d_in[21];
    float* out = (float*)d_out;

    void* p;
#define GETSYM(var, sym) cudaGetSymbolAddress(&p, sym); float* var = (float*)p;
    GETSYM(h1p,  g_h1)   GETSYM(h2p,  g_h2)   GETSYM(rp,   g_r)
    GETSYM(zep,  g_ze)   GETSYM(ekp,  g_ek)   GETSYM(d0p,  g_d0)
    GETSYM(d1p,  g_d1)
    GETSYM(wc1,  g_wc1)  GETSYM(wc2,  g_wc2)
    GETSYM(wr03, g_wr03) GETSYM(wr01, g_wr01)
    GETSYM(wr13, g_wr13) GETSYM(wr11, g_wr11)
    GETSYM(wtoz, g_wtoz) GETSYM(wfz,  g_wfz)  GETSYM(wt1, g_wt1)
#undef GETSYM

    // weight prep
    wtrans<<<(48*256 + 255) / 256, 256>>>(c1_w,  wc1,  256, 48);
    wtrans<<<(4096*256) / 256,     256>>>(c2_w,  wc2,  256, 4096);
    wtrans<<<(2304*256) / 256,     256>>>(r0_w3, wr03, 256, 2304);
    wtrans<<<(256*256)  / 256,     256>>>(r0_w1, wr01, 256, 256);
    wtrans<<<(2304*256) / 256,     256>>>(r1_w3, wr13, 256, 2304);
    wtrans<<<(256*256)  / 256,     256>>>(r1_w1, wr11, 256, 256);
    wtrans<<<(256*64)   / 256,     256>>>(toz_w, wtoz, 64,  256);
    wtrans<<<(64*256)   / 256,     256>>>(fz_w,  wfz,  256, 64);
    t1trans<<<(4*1024*256) / 256,  256>>>(t1_w, wt1);
    cbnorm_k<<<8, 64>>>(cb);

    // encoder
    conv_k<4,4,2,1,64,0,1,0><<<dim3(64,4,8), 256>>>(x,   wc1,  c1_b,  nullptr, h1p, 3,   128, 128, 4096, 256);
    conv_k<4,4,2,1,32,0,1,0><<<dim3(16,4,8), 256>>>(h1p, wc2,  c2_b,  nullptr, h2p, 256, 64,  64,  1024, 256);
    conv_k<3,3,1,1,32,1,0,0><<<dim3(16,4,8), 256>>>(h2p, wr03, r0_b3, nullptr, rp,  256, 32,  32,  1024, 256);
    conv_k<1,1,1,0,32,1,0,1><<<dim3(16,4,8), 256>>>(rp,  wr01, r0_b1, h2p,     h2p, 256, 32,  32,  1024, 256);
    conv_k<3,3,1,1,32,1,0,0><<<dim3(16,4,8), 256>>>(h2p, wr13, r1_b3, nullptr, rp,  256, 32,  32,  1024, 256);
    conv_k<1,1,1,0,32,1,0,1><<<dim3(16,4,8), 256>>>(rp,  wr11, r1_b1, h2p,     h2p, 256, 32,  32,  1024, 256);
    conv_k<1,1,1,0,32,0,0,0><<<dim3(16,1,8), 256>>>(h2p, wtoz, toz_b, nullptr, zep, 256, 32,  32,  1024, 64);

    // vector quantization
    vq_k<<<32, 256>>>(cb);

    // decoder
    conv_k<1,1,1,0,32,0,1,0><<<dim3(16,4,8), 256>>>(ekp, wfz, fz_b, nullptr, d0p, 64, 32, 32, 1024, 256);
    convt1_k<<<dim3(16,4,32), 256>>>(d0p, wt1, t1_b, d1p);
    t2_k<<<dim3(4,8,4), 256>>>(t2_w, t2_b, out);

    // pack z_e / e_k / ids
    pack_k<<<4128, 256>>>(out, out_size);
}

// round 5
// speedup vs baseline: 1.3862x; 1.3862x over previous
#include <cuda_runtime.h>
#include <cuda_fp16.h>
#include <cstdint>
#include <math.h>

// ================= static shapes =================
// B=8, HID=256, ZC=64, K=512
__device__ float g_h1[8*256*64*64];
__device__ float g_h2[8*256*32*32];
__device__ float g_r [8*256*32*32];
__device__ float g_ze[8*64*32*32];
__device__ float g_ek[8*64*32*32];
__device__ float g_d0[8*256*32*32];
__device__ float g_d1[8*256*64*64];
__device__ int   g_ids[8192];
__device__ float g_cbn[512];
__device__ float g_wc1 [48*256];
__device__ float g_wtoz[256*64];
__device__ float g_wfz [64*256];
__device__ float g_wt1b[4*256*1024];   // [cls][oc][ic*4+t]

// ================= mma helpers (base ISA, sm_80+) =================
__device__ __forceinline__ uint32_t smem_u32(const void* p) {
    uint32_t a;
    asm("{ .reg .u64 t; cvta.to.shared.u64 t, %1; cvt.u32.u64 %0, t; }" : "=r"(a) : "l"(p));
    return a;
}
#define LDSM_X4(r, addr) \
    asm volatile("ldmatrix.sync.aligned.m8n8.x4.shared.b16 {%0,%1,%2,%3}, [%4];" \
        : "=r"((r)[0]), "=r"((r)[1]), "=r"((r)[2]), "=r"((r)[3]) : "r"(addr))
#define MMA_F16(d, a, b) \
    asm volatile("mma.sync.aligned.m16n8k16.row.col.f32.f16.f16.f32 " \
        "{%0,%1,%2,%3}, {%4,%5,%6,%7}, {%8,%9}, {%0,%1,%2,%3};" \
        : "+f"((d)[0]), "+f"((d)[1]), "+f"((d)[2]), "+f"((d)[3]) \
        : "r"((a)[0]), "r"((a)[1]), "r"((a)[2]), "r"((a)[3]), "r"((b)[0]), "r"((b)[1]))

__device__ __forceinline__ void split2(float v0, float v1, uint32_t& hi, uint32_t& lo) {
    unsigned short h0 = __half_as_ushort(__float2half_rn(v0));
    unsigned short h1 = __half_as_ushort(__float2half_rn(v1));
    float r0 = v0 - __half2float(__ushort_as_half(h0));
    float r1 = v1 - __half2float(__ushort_as_half(h1));
    unsigned short l0 = __half_as_ushort(__float2half_rn(r0));
    unsigned short l1 = __half_as_ushort(__float2half_rn(r1));
    hi = (uint32_t)h0 | ((uint32_t)h1 << 16);
    lo = (uint32_t)l0 | ((uint32_t)l1 << 16);
}

// ================= prep kernels =================
__global__ void wtrans(const float* __restrict__ src, float* __restrict__ dst,
                       int Cout, int K) {
    int i = blockIdx.x * 256 + threadIdx.x;
    if (i >= Cout * K) return;
    int k = i / Cout, oc = i - k * Cout;
    dst[i] = src[(size_t)oc * K + k];
}
__global__ void t1prep(const float* __restrict__ w, float* __restrict__ dst) {
    int i = blockIdx.x * 256 + threadIdx.x;   // 4*256*1024
    int cls = i >> 18;
    int r = i & 262143;
    int oc = r >> 10, k = r & 1023;
    int ic = k >> 2, t = k & 3;
    int a = t >> 1, bb = t & 1;
    int ry = cls >> 1, rx = cls & 1;
    int ky = ry ? (a ? 2 : 0) : (a ? 3 : 1);
    int kx = rx ? (bb ? 2 : 0) : (bb ? 3 : 1);
    dst[i] = w[((size_t)(ic * 256 + oc)) * 16 + ky * 4 + kx];
}
__global__ void cbnorm_k(const float* __restrict__ cb) {
    int k = blockIdx.x * 64 + threadIdx.x;
    if (k >= 512) return;
    const float* r = cb + (size_t)k * 64;
    float s0 = 0, s1 = 0, s2 = 0, s3 = 0;
#pragma unroll
    for (int c = 0; c < 64; c += 4) {
        s0 += r[c]*r[c]; s1 += r[c+1]*r[c+1]; s2 += r[c+2]*r[c+2]; s3 += r[c+3]*r[c+3];
    }
    g_cbn[k] = (s0 + s1) + (s2 + s3);
}

// ================= tensor-core conv (mma.sync fp16-split-3) =================
// C[m=spatial 128][n=oc 128] tiles, BK=32 fp32 per stage, double-buffered.
// SMEM row (per m or n): 128B = [32 hi fp16][32 lo fp16], 16B-chunk XOR-8 swizzle.
// MODE 0: standard conv (out 32x32/img). MODE 1: t1 parity-class GEMM.
template<int MODE, int T, int KW, int STR, int PAD, int IH, int IW,
         int RIN, int ROUT, int ADDRES>
__global__ __launch_bounds__(256) void tconv(
    const float* __restrict__ in, const float* __restrict__ wg0,
    const float* __restrict__ bias, const float* __restrict__ res,
    float* __restrict__ out, int K, int Cout, float SA, float SW, float SINV)
{
    extern __shared__ __align__(128) char smem[];
    const uint32_t sb0 = (smem_u32(smem) + 127) & ~127u;
    const int tid = threadIdx.x, lane = tid & 31, wid = tid >> 5;
    const int zi = blockIdx.z;
    int b, ry = 0, rx = 0, oy0 = 0, oy1 = 0, ox0 = 0, ox1 = 0;
    const float* wg = wg0;
    if (MODE == 1) {
        b = zi >> 2; int cls = zi & 3;
        ry = cls >> 1; rx = cls & 1;
        oy0 = ry ? 1 : 0; oy1 = ry ? 0 : -1;
        ox0 = rx ? 1 : 0; ox1 = rx ? 0 : -1;
        wg = wg0 + (size_t)cls * 262144;
    } else b = zi;
    const int m0 = blockIdx.x * 128;
    const int n0 = blockIdx.y * 128;
    const int Cin = (MODE == 1) ? 256 : K / T;
    const float* inb = in + (size_t)b * Cin * IH * IW;

    float stA[8][2], stB[8][2];

    auto LOADG = [&](int s) {
        const int k0 = s << 5;
#pragma unroll
        for (int i = 0; i < 8; i++) {
            int kp  = (lane >> 3) | ((i & 3) << 2);
            int row = (lane & 7) | (wid << 3) | ((i >> 2) << 6);
            int m = m0 + row;
            float v0, v1;
            if (MODE == 1) {
                int y = m >> 5, x = m & 31;
#pragma unroll
                for (int j = 0; j < 2; j++) {
                    int k = k0 + 2 * kp + j;
                    int ic = k >> 2, t = k & 3;
                    int iy = y + ((t & 2) ? oy1 : oy0);
                    int ix = x + ((t & 1) ? ox1 : ox0);
                    float v = 0.f;
                    if ((unsigned)iy < 32u && (unsigned)ix < 32u)
                        v = inb[ic * 1024 + iy * 32 + ix];
                    (j ? v1 : v0) = v;
                }
            } else if (T == 1) {
                int k = k0 + 2 * kp;
                v0 = inb[(size_t)k * 1024 + m];
                v1 = inb[(size_t)(k + 1) * 1024 + m];
            } else {
                int ay = m >> 5, ax = m & 31;
                int yb = ay * STR - PAD, xb = ax * STR - PAD;
#pragma unroll
                for (int j = 0; j < 2; j++) {
                    int k = k0 + 2 * kp + j;
                    int ic = k / T, tap = k - ic * T;
                    int ky = tap / KW, kx = tap - ky * KW;
                    int iy = yb + ky, ix = xb + kx;
                    float v = 0.f;
                    if ((unsigned)iy < (unsigned)IH && (unsigned)ix < (unsigned)IW)
                        v = inb[(size_t)ic * (IH * IW) + iy * IW + ix];
                    (j ? v1 : v0) = v;
                }
            }
            if (RIN) { v0 = fmaxf(v0, 0.f); v1 = fmaxf(v1, 0.f); }
            stA[i][0] = v0 * SA; stA[i][1] = v1 * SA;
            float2 f2 = *(const float2*)(wg + (size_t)(n0 + row) * K + k0 + 2 * kp);
            stB[i][0] = f2.x * SW; stB[i][1] = f2.y * SW;
        }
    };
    auto STORE = [&](int bufid) {
        const uint32_t Ab = sb0 + bufid * 32768, Bb = Ab + 16384;
#pragma unroll
        for (int i = 0; i < 8; i++) {
            int kp  = (lane >> 3) | ((i & 3) << 2);
            int row = (lane & 7) | (wid << 3) | ((i >> 2) << 6);
            uint32_t c = kp >> 2, w = kp & 3;
            uint32_t offH = (uint32_t)row * 128 + ((c ^ (row & 7)) << 4) + (w << 2);
            uint32_t offL = (uint32_t)row * 128 + (((c + 4) ^ (row & 7)) << 4) + (w << 2);
            uint32_t hi, lo;
            split2(stA[i][0], stA[i][1], hi, lo);
            asm volatile("st.shared.b32 [%0], %1;" :: "r"(Ab + offH), "r"(hi) : "memory");
            asm volatile("st.shared.b32 [%0], %1;" :: "r"(Ab + offL), "r"(lo) : "memory");
            split2(stB[i][0], stB[i][1], hi, lo);
            asm volatile("st.shared.b32 [%0], %1;" :: "r"(Bb + offH), "r"(hi) : "memory");
            asm volatile("st.shared.b32 [%0], %1;" :: "r"(Bb + offL), "r"(lo) : "memory");
        }
    };

    const int wm = wid & 3, wn = wid >> 2;
    float acc[2][8][4] = {};
    const int rl = lane & 15, kc = lane >> 4;

    const int NS = K >> 5;
    LOADG(0); STORE(0); __syncthreads();
    for (int s = 0; s < NS; s++) {
        if (s + 1 < NS) LOADG(s + 1);
        const uint32_t Ab = sb0 + (s & 1) * 32768, Bb = Ab + 16384;
#pragma unroll
        for (int g = 0; g < 2; g++) {
            uint32_t aH[2][4], aL[2][4];
#pragma unroll
            for (int mt = 0; mt < 2; mt++) {
                int r = wm * 32 + mt * 16 + rl;
                uint32_t base = Ab + (uint32_t)r * 128;
                int cH = 2 * g + kc;
                LDSM_X4(aH[mt], base + (uint32_t)((cH ^ (r & 7)) << 4));
                LDSM_X4(aL[mt], base + (uint32_t)(((cH + 4) ^ (r & 7)) << 4));
            }
            uint32_t bH[8][2], bL[8][2];
#pragma unroll
            for (int t = 0; t < 4; t++) {
                int r = wn * 64 + t * 16 + rl;
                uint32_t base = Bb + (uint32_t)r * 128;
                int cH = 2 * g + kc;
                uint32_t q[4];
                LDSM_X4(q, base + (uint32_t)((cH ^ (r & 7)) << 4));
                bH[2*t][0] = q[0]; bH[2*t+1][0] = q[1]; bH[2*t][1] = q[2]; bH[2*t+1][1] = q[3];
                LDSM_X4(q, base + (uint32_t)(((cH + 4) ^ (r & 7)) << 4));
                bL[2*t][0] = q[0]; bL[2*t+1][0] = q[1]; bL[2*t][1] = q[2]; bL[2*t+1][1] = q[3];
            }
#pragma unroll
            for (int mt = 0; mt < 2; mt++)
#pragma unroll
                for (int nt = 0; nt < 8; nt++) {
                    MMA_F16(acc[mt][nt], aH[mt], bH[nt]);
                    MMA_F16(acc[mt][nt], aH[mt], bL[nt]);
                    MMA_F16(acc[mt][nt], aL[mt], bH[nt]);
                }
        }
        if (s + 1 < NS) STORE((s + 1) & 1);
        __syncthreads();
    }

    // ---- epilogue: scale back, bias, residual, relu, store
#pragma unroll
    for (int mt = 0; mt < 2; mt++) {
        int mb = m0 + wm * 32 + mt * 16 + (lane >> 2);
#pragma unroll
        for (int nt = 0; nt < 8; nt++) {
            int ocb = n0 + wn * 64 + nt * 8 + ((lane & 3) << 1);
#pragma unroll
            for (int h = 0; h < 2; h++) {
                int m = mb + h * 8;
#pragma unroll
                for (int q = 0; q < 2; q++) {
                    int oc = ocb + q;
                    float v = acc[mt][nt][h * 2 + q] * SINV + __ldg(bias + oc);
                    size_t ob;
                    if (MODE == 1) {
                        int y = m >> 5, x = m & 31;
                        ob = ((size_t)(b * Cout + oc)) * 4096 + (size_t)(2*y + ry) * 64 + (2*x + rx);
                    } else {
                        ob = ((size_t)b * Cout + oc) * 1024 + m;
                    }
                    if (ADDRES) v += res[ob];
                    if (ROUT) v = fmaxf(v, 0.f);
                    out[ob] = v;
                }
            }
        }
    }
}

// ================= fp32 implicit-GEMM conv (small layers) =================
#define FMA16 \
    acc[0][0] += bv.x*a.x; acc[0][1] += bv.x*a.y; acc[0][2] += bv.x*a.z; acc[0][3] += bv.x*a.w; \
    acc[1][0] += bv.y*a.x; acc[1][1] += bv.y*a.y; acc[1][2] += bv.y*a.z; acc[1][3] += bv.y*a.w; \
    acc[2][0] += bv.z*a.x; acc[2][1] += bv.z*a.y; acc[2][2] += bv.z*a.z; acc[2][3] += bv.z*a.w; \
    acc[3][0] += bv.w*a.x; acc[3][1] += bv.w*a.y; acc[3][2] += bv.w*a.z; acc[3][3] += bv.w*a.w;

template<int KH, int KW, int STR, int PAD, int OW, int RIN, int ROUT, int ADDRES>
__global__ __launch_bounds__(256) void conv_k(
    const float* __restrict__ in, const float* __restrict__ wT,
    const float* __restrict__ bias, const float* __restrict__ res,
    float* __restrict__ out, int Cin, int IH, int IW, int MIMG, int Cout)
{
    constexpr int T = KH * KW;
    const int K  = Cin * T;
    const int b  = blockIdx.z;
    const int m0 = blockIdx.x * 64;
    const int n0 = blockIdx.y * 64;
    __shared__ float As[16][64];
    __shared__ float Bs[16][64];
    const int tid = threadIdx.x;
    const int lm = tid & 63, lk = tid >> 6;
    const int mi = (tid & 15) << 2, ni = (tid >> 4) << 2;

    const int am = m0 + lm;
    const int ay = am / OW, ax = am % OW;
    const int ybase = ay * STR - PAD, xbase = ax * STR - PAD;
    const float* inb = in + (size_t)b * Cin * IH * IW;

    float acc[4][4] = {};
    for (int k0 = 0; k0 < K; k0 += 16) {
#pragma unroll
        for (int i = 0; i < 4; i++) {
            int k   = k0 + lk + i * 4;
            int ic  = k / T;
            int tap = k - ic * T;
            int ky  = tap / KW;
            int kx  = tap - ky * KW;
            int iy = ybase + ky, ix = xbase + kx;
            float v = 0.f;
            if ((unsigned)iy < (unsigned)IH && (unsigned)ix < (unsigned)IW)
                v = inb[(size_t)ic * IH * IW + iy * IW + ix];
            if (RIN) v = fmaxf(v, 0.f);
            As[lk + i * 4][lm] = v;
            Bs[lk + i * 4][lm] = wT[(size_t)k * Cout + n0 + lm];
        }
        __syncthreads();
#pragma unroll
        for (int kk = 0; kk < 16; kk++) {
            float4 a  = *(const float4*)&As[kk][mi];
            float4 bv = *(const float4*)&Bs[kk][ni];
            FMA16
        }
        __syncthreads();
    }
    const int m = m0 + mi;
#pragma unroll
    for (int i = 0; i < 4; i++) {
        int oc = n0 + ni + i;
        size_t ob = ((size_t)b * Cout + oc) * MIMG + m;
        float bb = bias[oc];
        float4 r;
        r.x = acc[i][0] + bb; r.y = acc[i][1] + bb;
        r.z = acc[i][2] + bb; r.w = acc[i][3] + bb;
        if (ADDRES) {
            float4 rv = *(const float4*)&res[ob];
            r.x += rv.x; r.y += rv.y; r.z += rv.z; r.w += rv.w;
        }
        if (ROUT) {
            r.x = fmaxf(r.x, 0.f); r.y = fmaxf(r.y, 0.f);
            r.z = fmaxf(r.z, 0.f); r.w = fmaxf(r.w, 0.f);
        }
        *(float4*)&out[ob] = r;
    }
}

// ================= t2 (256 -> 3, 64x64 -> 128x128) + sigmoid =================
__global__ __launch_bounds__(256) void t2_k(const float* __restrict__ w,
                                            const float* __restrict__ bias,
                                            float* __restrict__ out)
{
    const int cls = blockIdx.z, b = blockIdx.y;
    const int ry = cls >> 1, rx = cls & 1;
    const int oy0 = ry ? 1 : 0, oy1 = ry ? 0 : -1;
    const int ox1 = rx ? 0 : -1;
    __shared__ float ws[3072];
    for (int i = threadIdx.x; i < 3072; i += 256) {
        int ic = i / 12, r = i - ic * 12;
        int t = r / 3, oc = r - t * 3;
        int a = t >> 1, bb = t & 1;
        int ky = ry ? (a ? 2 : 0) : (a ? 3 : 1);
        int kx = rx ? (bb ? 2 : 0) : (bb ? 3 : 1);
        ws[i] = w[((size_t)(ic * 3 + oc)) * 16 + ky * 4 + kx];
    }
    __syncthreads();
    const int t = blockIdx.x * 256 + threadIdx.x;
    const int yy = t >> 4;
    const int xg = (t & 15) << 2;
    const int basex = xg + ox1;
    const float* inb = g_d1 + (size_t)b * 256 * 4096;
    float acc[4][3] = {};
    for (int ic = 0; ic < 256; ic++) {
        const float* ip = inb + ic * 4096;
        float v[2][5];
#pragma unroll
        for (int a = 0; a < 2; a++) {
            int iy = yy + (a ? oy1 : oy0);
            bool okr = (unsigned)iy < 64u;
#pragma unroll
            for (int q = 0; q < 5; q++) {
                int ix = basex + q;
                v[a][q] = (okr && (unsigned)ix < 64u) ? ip[iy * 64 + ix] : 0.f;
            }
        }
        const float* wr = &ws[ic * 12];
#pragma unroll
        for (int p = 0; p < 4; p++)
#pragma unroll
            for (int bb2 = 0; bb2 < 2; bb2++) {
#pragma unroll
                for (int a = 0; a < 2; a++) {
                    float val = v[a][p + (bb2 ? 0 : 1)];
                    int ti = a * 2 + bb2;
                    acc[p][0] += val * wr[ti * 3 + 0];
                    acc[p][1] += val * wr[ti * 3 + 1];
                    acc[p][2] += val * wr[ti * 3 + 2];
                }
            }
    }
#pragma unroll
    for (int p = 0; p < 4; p++) {
        int oy = 2 * yy + ry, ox = 2 * (xg + p) + rx;
#pragma unroll
        for (int oc = 0; oc < 3; oc++) {
            float vv = acc[p][oc] + bias[oc];
            out[((size_t)(b * 3 + oc) * 128 + oy) * 128 + ox] = 1.f / (1.f + __expf(-vv));
        }
    }
}

// ================= VQ =================
__global__ __launch_bounds__(256) void vq_k(const float* __restrict__ cb)
{
    const int n = blockIdx.x * 256 + threadIdx.x;
    const int b = n >> 10, s = n & 1023;
    const float* zp = g_ze + (size_t)b * 64 * 1024 + s;
    float z[64];
#pragma unroll
    for (int c = 0; c < 64; c++) z[c] = zp[(size_t)c * 1024];
    float z0 = 0, z1 = 0, z2a = 0, z3 = 0;
#pragma unroll
    for (int c = 0; c < 64; c += 4) {
        z0 += z[c]*z[c]; z1 += z[c+1]*z[c+1]; z2a += z[c+2]*z[c+2]; z3 += z[c+3]*z[c+3];
    }
    const float zn = (z0 + z1) + (z2a + z3);
    __shared__ float cbs[4096];
    float best = 3.4e38f; int bid = 0;
    for (int c0 = 0; c0 < 512; c0 += 64) {
        __syncthreads();
#pragma unroll
        for (int i = 0; i < 16; i++)
            cbs[threadIdx.x + i * 256] = cb[(size_t)c0 * 64 + threadIdx.x + i * 256];
        __syncthreads();
        for (int k = 0; k < 64; k++) {
            const float* cr = &cbs[k * 64];
            float d0 = 0, d1 = 0, d2 = 0, d3 = 0;
#pragma unroll
            for (int c = 0; c < 64; c += 4) {
                d0 += z[c]*cr[c]; d1 += z[c+1]*cr[c+1]; d2 += z[c+2]*cr[c+2]; d3 += z[c+3]*cr[c+3];
            }
            float dot = (d0 + d1) + (d2 + d3);
            float score = (zn - 2.0f * dot) + g_cbn[c0 + k];
            if (score < best) { best = score; bid = c0 + k; }
        }
    }
    g_ids[n] = bid;
    const float* code = cb + (size_t)bid * 64;
    float* ep = g_ek + (size_t)b * 64 * 1024 + s;
#pragma unroll
    for (int c = 0; c < 64; c++) ep[(size_t)c * 1024] = code[c];
}

// ================= pack tuple tail =================
__global__ void pack_k(float* __restrict__ out, int out_size)
{
    int i = blockIdx.x * 256 + threadIdx.x;
    if (i < 524288) {
        int o = 393216 + i;
        if (o < out_size) out[o] = g_ze[i];
    } else if (i < 1048576) {
        int j = i - 524288;
        int o = 917504 + j;
        if (o < out_size) out[o] = g_ek[j];
    } else if (i < 1056768) {
        int j = i - 1048576;
        int o = 1441792 + j;
        if (o < out_size) out[o] = (float)g_ids[j];
    }
}

// ================= launch =================
static constexpr int SMEM_TC = 65536 + 256;

extern "C" void kernel_launch(void* const* d_in, const int* in_sizes, int n_in,
                              void* d_out, int out_size)
{
    const float* x     = (const float*)d_in[0];
    const float* c1_w  = (const float*)d_in[1];
    const float* c1_b  = (const float*)d_in[2];
    const float* c2_w  = (const float*)d_in[3];
    const float* c2_b  = (const float*)d_in[4];
    const float* r0_w3 = (const float*)d_in[5];
    const float* r0_b3 = (const float*)d_in[6];
    const float* r0_w1 = (const float*)d_in[7];
    const float* r0_b1 = (const float*)d_in[8];
    const float* r1_w3 = (const float*)d_in[9];
    const float* r1_b3 = (const float*)d_in[10];
    const float* r1_w1 = (const float*)d_in[11];
    const float* r1_b1 = (const float*)d_in[12];
    const float* toz_w = (const float*)d_in[13];
    const float* toz_b = (const float*)d_in[14];
    const float* cb    = (const float*)d_in[15];
    const float* fz_w  = (const float*)d_in[16];
    const float* fz_b  = (const float*)d_in[17];
    const float* t1_w  = (const float*)d_in[18];
    const float* t1_b  = (const float*)d_in[19];
    const float* t2_w  = (const float*)d_in[20];
    const float* t2_b  = (const float*)d_in[21];
    float* out = (float*)d_out;

    void* p;
#define GETSYM(var, sym) cudaGetSymbolAddress(&p, sym); float* var = (float*)p;
    GETSYM(h1p,  g_h1)   GETSYM(h2p,  g_h2)   GETSYM(rp,   g_r)
    GETSYM(zep,  g_ze)   GETSYM(ekp,  g_ek)   GETSYM(d0p,  g_d0)
    GETSYM(d1p,  g_d1)
    GETSYM(wc1,  g_wc1)  GETSYM(wtoz, g_wtoz) GETSYM(wfz,  g_wfz)
    GETSYM(wt1b, g_wt1b)
#undef GETSYM

    auto* kc2 = tconv<0, 16, 4, 2, 1, 64, 64, 0, 1, 0>;
    auto* kr3 = tconv<0,  9, 3, 1, 1, 32, 32, 1, 0, 0>;
    auto* kr1 = tconv<0,  1, 1, 1, 0, 32, 32, 1, 0, 1>;
    auto* kt1 = tconv<1,  4, 1, 1, 0, 32, 32, 0, 1, 0>;
    cudaFuncSetAttribute(kc2, cudaFuncAttributeMaxDynamicSharedMemorySize, SMEM_TC);
    cudaFuncSetAttribute(kr3, cudaFuncAttributeMaxDynamicSharedMemorySize, SMEM_TC);
    cudaFuncSetAttribute(kr1, cudaFuncAttributeMaxDynamicSharedMemorySize, SMEM_TC);
    cudaFuncSetAttribute(kt1, cudaFuncAttributeMaxDynamicSharedMemorySize, SMEM_TC);

    // weight prep
    wtrans<<<(48*256 + 255) / 256, 256>>>(c1_w,  wc1,  256, 48);
    wtrans<<<(256*64)   / 256,     256>>>(toz_w, wtoz, 64,  256);
    wtrans<<<(64*256)   / 256,     256>>>(fz_w,  wfz,  256, 64);
    t1prep<<<(4*256*1024) / 256,   256>>>(t1_w, wt1b);
    cbnorm_k<<<8, 64>>>(cb);

    const float SA = 256.f, SW = 1024.f;
    const float SI = 1.f / (256.f * 1024.f);
    const float SAT = 16384.f, SIT = 1.f / (16384.f * 1024.f);

    // encoder
    conv_k<4,4,2,1,64,0,1,0><<<dim3(64,4,8), 256>>>(x, wc1, c1_b, nullptr, h1p, 3, 128, 128, 4096, 256);
    kc2<<<dim3(8,2,8),  256, SMEM_TC>>>(h1p, c2_w,  c2_b,  nullptr, h2p, 4096, 256, SA, SW, SI);
    kr3<<<dim3(8,2,8),  256, SMEM_TC>>>(h2p, r0_w3, r0_b3, nullptr, rp,  2304, 256, SA, SW, SI);
    kr1<<<dim3(8,2,8),  256, SMEM_TC>>>(rp,  r0_w1, r0_b1, h2p,     h2p, 256,  256, SA, SW, SI);
    kr3<<<dim3(8,2,8),  256, SMEM_TC>>>(h2p, r1_w3, r1_b3, nullptr, rp,  2304, 256, SA, SW, SI);
    kr1<<<dim3(8,2,8),  256, SMEM_TC>>>(rp,  r1_w1, r1_b1, h2p,     h2p, 256,  256, SA, SW, SI);
    conv_k<1,1,1,0,32,0,0,0><<<dim3(16,1,8), 256>>>(h2p, wtoz, toz_b, nullptr, zep, 256, 32, 32, 1024, 64);

    // vector quantization
    vq_k<<<32, 256>>>(cb);

    // decoder
    conv_k<1,1,1,0,32,0,1,0><<<dim3(16,4,8), 256>>>(ekp, wfz, fz_b, nullptr, d0p, 64, 32, 32, 1024, 256);
    kt1<<<dim3(8,2,32), 256, SMEM_TC>>>(d0p, wt1b, t1_b, nullptr, d1p, 1024, 256, SAT, SW, SIT);
    t2_k<<<dim3(4,8,4), 256>>>(t2_w, t2_b, out);

    // pack z_e / e_k / ids
    pack_k<<<4128, 256>>>(out, out_size);
}

// round 7
// speedup vs baseline: 1.9339x; 1.3951x over previous
#include <cuda_runtime.h>
#include <cuda_fp16.h>
#include <cstdint>
#include <math.h>

// ================= static shapes =================
// B=8, HID=256, ZC=64, K=512
__device__ float    g_h2[8*256*32*32];       // fp32 h2 (residual / toz input)
__device__ float    g_ze[8*64*32*32];
__device__ float    g_ek[8*64*32*32];
__device__ float    g_d1[8*256*64*64];
__device__ int      g_ids[8192];
__device__ float    g_cbn[512];
__device__ float    g_wc1 [48*256];
__device__ float    g_wtoz[256*64];
__device__ float    g_wfz [64*256];
// split activations (u32 = hi16<<16 | lo16), pre-scaled, post-relu
__device__ uint32_t g_h1s [8*256*64*64];
__device__ uint32_t g_acts[8*256*32*32];
__device__ uint32_t g_rs  [8*256*32*32];
__device__ uint32_t g_d0s [8*256*32*32];
// split weights, per-stage chunk layout: [(s*256+oc)*8+c]*4+w ; c<4 hi, c>=4 lo
__device__ uint32_t g_wc2s [256*4096];
__device__ uint32_t g_wr03s[256*2304];
__device__ uint32_t g_wr01s[256*256];
__device__ uint32_t g_wr13s[256*2304];
__device__ uint32_t g_wr11s[256*256];
__device__ uint32_t g_wt1s [4*256*1024];

// ================= helpers =================
__device__ __forceinline__ uint32_t smem_u32(const void* p) {
    uint32_t a;
    asm("{ .reg .u64 t; cvta.to.shared.u64 t, %1; cvt.u32.u64 %0, t; }" : "=r"(a) : "l"(p));
    return a;
}
#define LDSM_X4(r, addr) \
    asm volatile("ldmatrix.sync.aligned.m8n8.x4.shared.b16 {%0,%1,%2,%3}, [%4];" \
        : "=r"((r)[0]), "=r"((r)[1]), "=r"((r)[2]), "=r"((r)[3]) : "r"(addr))
#define MMA_F16(d, a, b) \
    asm volatile("mma.sync.aligned.m16n8k16.row.col.f32.f16.f16.f32 " \
        "{%0,%1,%2,%3}, {%4,%5,%6,%7}, {%8,%9}, {%0,%1,%2,%3};" \
        : "+f"((d)[0]), "+f"((d)[1]), "+f"((d)[2]), "+f"((d)[3]) \
        : "r"((a)[0]), "r"((a)[1]), "r"((a)[2]), "r"((a)[3]), "r"((b)[0]), "r"((b)[1]))
#define CP_ASYNC16(dst, src) \
    asm volatile("cp.async.cg.shared.global [%0], [%1], 16;" :: "r"(dst), "l"(src) : "memory")
#define CP_COMMIT()  asm volatile("cp.async.commit_group;" ::: "memory")
#define CP_WAIT0()   asm volatile("cp.async.wait_group 0;" ::: "memory")

__device__ __forceinline__ uint32_t splitpack(float v) {
    unsigned short h = __half_as_ushort(__float2half_rn(v));
    float r = v - __half2float(__ushort_as_half(h));
    unsigned short l = __half_as_ushort(__float2half_rn(r));
    return ((uint32_t)h << 16) | (uint32_t)l;
}

// ================= prep kernels =================
__global__ void wtrans(const float* __restrict__ src, float* __restrict__ dst,
                       int Cout, int K) {
    int i = blockIdx.x * 256 + threadIdx.x;
    if (i >= Cout * K) return;
    int k = i / Cout, oc = i - k * Cout;
    dst[i] = src[(size_t)oc * K + k];
}
// split weights into per-stage chunk layout
__global__ void wsplit(const float* __restrict__ src, uint32_t* __restrict__ dst,
                       int K, float SW) {
    int u = blockIdx.x * 256 + threadIdx.x;
    if (u >= 256 * K) return;
    int w = u & 3, c = (u >> 2) & 7, oc = (u >> 5) & 255, s = u >> 13;
    int kb = 32 * s + 8 * (c & 3) + 2 * w;
    float v0 = src[(size_t)oc * K + kb] * SW;
    float v1 = src[(size_t)oc * K + kb + 1] * SW;
    unsigned short h0 = __half_as_ushort(__float2half_rn(v0));
    unsigned short h1 = __half_as_ushort(__float2half_rn(v1));
    uint32_t val;
    if (c < 4) val = (uint32_t)h0 | ((uint32_t)h1 << 16);
    else {
        unsigned short l0 = __half_as_ushort(__float2half_rn(v0 - __half2float(__ushort_as_half(h0))));
        unsigned short l1 = __half_as_ushort(__float2half_rn(v1 - __half2float(__ushort_as_half(h1))));
        val = (uint32_t)l0 | ((uint32_t)l1 << 16);
    }
    dst[u] = val;
}
// t1: remap ConvTranspose weights per parity class, then split (fused)
__global__ void wt1split(const float* __restrict__ w, uint32_t* __restrict__ dst, float SW) {
    int u = blockIdx.x * 256 + threadIdx.x;   // 4*256*1024
    int cls = u >> 18;
    int r = u & 262143;
    int ww = r & 3, c = (r >> 2) & 7, oc = (r >> 5) & 255, s = r >> 13;
    int ry = cls >> 1, rx = cls & 1;
    int kb = 32 * s + 8 * (c & 3) + 2 * ww;
    float v[2];
#pragma unroll
    for (int j = 0; j < 2; j++) {
        int k = kb + j;
        int ic = k >> 2, t = k & 3;
        int a = t >> 1, bb = t & 1;
        int ky = ry ? (a ? 2 : 0) : (a ? 3 : 1);
        int kx = rx ? (bb ? 2 : 0) : (bb ? 3 : 1);
        v[j] = w[((size_t)(ic * 256 + oc)) * 16 + ky * 4 + kx] * SW;
    }
    unsigned short h0 = __half_as_ushort(__float2half_rn(v[0]));
    unsigned short h1 = __half_as_ushort(__float2half_rn(v[1]));
    uint32_t val;
    if (c < 4) val = (uint32_t)h0 | ((uint32_t)h1 << 16);
    else {
        unsigned short l0 = __half_as_ushort(__float2half_rn(v[0] - __half2float(__ushort_as_half(h0))));
        unsigned short l1 = __half_as_ushort(__float2half_rn(v[1] - __half2float(__ushort_as_half(h1))));
        val = (uint32_t)l0 | ((uint32_t)l1 << 16);
    }
    dst[u] = val;
}
__global__ void cbnorm_k(const float* __restrict__ cb) {
    int k = blockIdx.x * 64 + threadIdx.x;
    if (k >= 512) return;
    const float* r = cb + (size_t)k * 64;
    float s0 = 0, s1 = 0, s2 = 0, s3 = 0;
#pragma unroll
    for (int c = 0; c < 64; c += 4) {
        s0 += r[c]*r[c]; s1 += r[c+1]*r[c+1]; s2 += r[c+2]*r[c+2]; s3 += r[c+3]*r[c+3];
    }
    g_cbn[k] = (s0 + s1) + (s2 + s3);
}

// ================= tensor-core conv (mma.sync fp16-split-3) =================
// A: gather pre-split u32 activations; B: cp.async pre-split weights.
// MODE 0: standard conv. MODE 1: t1 parity-class GEMM (scatter epilogue).
template<int MODE, int T, int KW, int STR, int PAD, int IH, int IW,
         int OUTF, int OUTS, int ADDRES, int ROUT>
__global__ __launch_bounds__(256) void tconv(
    const uint32_t* __restrict__ inS, const uint32_t* __restrict__ wS,
    const float* __restrict__ bias, const float* __restrict__ res,
    float* __restrict__ outF, uint32_t* __restrict__ outS,
    int K, int Cout, float SINV, float SAN)
{
    extern __shared__ __align__(128) char smem[];
    const uint32_t sb0 = (smem_u32(smem) + 127) & ~127u;
    const int tid = threadIdx.x, lane = tid & 31, wid = tid >> 5;
    const int zi = blockIdx.z;
    int b, ry = 0, rx = 0, oy0 = 0, oy1 = 0, ox0 = 0, ox1 = 0;
    const uint32_t* wg = wS;
    if (MODE == 1) {
        b = zi >> 2; int cls = zi & 3;
        ry = cls >> 1; rx = cls & 1;
        oy0 = ry ? 1 : 0; oy1 = ry ? 0 : -1;
        ox0 = rx ? 1 : 0; ox1 = rx ? 0 : -1;
        wg = wS + (size_t)cls * 262144;
    } else b = zi;
    const int m0 = blockIdx.x * 128;
    const int n0 = blockIdx.y * 128;
    const int Cin = (MODE == 1) ? 256 : K / T;
    const uint32_t* inb = inS + (size_t)b * Cin * IH * IW;

    uint32_t stA[8][2];

    auto GA = [&](int s) {
        const int k0 = s << 5;
#pragma unroll
        for (int i = 0; i < 8; i++) {
            int kp  = (lane >> 3) | ((i & 3) << 2);
            int row = (lane & 7) | (wid << 3) | ((i >> 2) << 6);
            int m = m0 + row;
            uint32_t e0, e1;
            if (MODE == 1) {
                int y = m >> 5, x = m & 31;
#pragma unroll
                for (int j = 0; j < 2; j++) {
                    int k = k0 + 2 * kp + j;
                    int ic = k >> 2, t = k & 3;
                    int iy = y + ((t & 2) ? oy1 : oy0);
                    int ix = x + ((t & 1) ? ox1 : ox0);
                    uint32_t e = 0;
                    if ((unsigned)iy < 32u && (unsigned)ix < 32u)
                        e = inb[ic * 1024 + iy * 32 + ix];
                    (j ? e1 : e0) = e;
                }
            } else if (T == 1) {
                int k = k0 + 2 * kp;
                e0 = inb[(size_t)k * 1024 + m];
                e1 = inb[(size_t)(k + 1) * 1024 + m];
            } else {
                int ay = m >> 5, ax = m & 31;
                int yb = ay * STR - PAD, xb = ax * STR - PAD;
#pragma unroll
                for (int j = 0; j < 2; j++) {
                    int k = k0 + 2 * kp + j;
                    int ic = k / T, tap = k - ic * T;
                    int ky = tap / KW, kx = tap - ky * KW;
                    int iy = yb + ky, ix = xb + kx;
                    uint32_t e = 0;
                    if ((unsigned)iy < (unsigned)IH && (unsigned)ix < (unsigned)IW)
                        e = inb[(size_t)ic * (IH * IW) + iy * IW + ix];
                    (j ? e1 : e0) = e;
                }
            }
            stA[i][0] = __byte_perm(e0, e1, 0x7632);  // hi pair
            stA[i][1] = __byte_perm(e0, e1, 0x5410);  // lo pair
        }
    };
    auto STA = [&](int bufid) {
        const uint32_t Ab = sb0 + bufid * 32768;
#pragma unroll
        for (int i = 0; i < 8; i++) {
            int kp  = (lane >> 3) | ((i & 3) << 2);
            int row = (lane & 7) | (wid << 3) | ((i >> 2) << 6);
            uint32_t c = kp >> 2, w = kp & 3;
            uint32_t offH = (uint32_t)row * 128 + ((c ^ (row & 7)) << 4) + (w << 2);
            uint32_t offL = (uint32_t)row * 128 + (((c + 4) ^ (row & 7)) << 4) + (w << 2);
            asm volatile("st.shared.b32 [%0], %1;" :: "r"(Ab + offH), "r"(stA[i][0]) : "memory");
            asm volatile("st.shared.b32 [%0], %1;" :: "r"(Ab + offL), "r"(stA[i][1]) : "memory");
        }
    };
    auto GB = [&](int s, int bufid) {
        const uint32_t Bb = sb0 + bufid * 32768 + 16384;
#pragma unroll
        for (int i = 0; i < 4; i++) {
            int q = tid + i * 256;
            int r = q >> 3, cc = q & 7;
            const uint32_t* src = wg + (((size_t)s * 256 + n0 + r) * 8 + cc) * 4;
            uint32_t dst = Bb + (uint32_t)r * 128 + ((uint32_t)(cc ^ (r & 7)) << 4);
            CP_ASYNC16(dst, src);
        }
        CP_COMMIT();
    };

    const int wm = wid & 3, wn = wid >> 2;
    float acc[2][8][4] = {};
    const int rl = lane & 15, kc = lane >> 4;

    const int NS = K >> 5;
    GB(0, 0); GA(0); STA(0);
    CP_WAIT0();
    __syncthreads();
    for (int s = 0; s < NS; s++) {
        if (s + 1 < NS) { GB(s + 1, (s + 1) & 1); GA(s + 1); }
        const uint32_t Ab = sb0 + (s & 1) * 32768, Bb = Ab + 16384;
#pragma unroll
        for (int g = 0; g < 2; g++) {
            uint32_t aH[2][4], aL[2][4];
#pragma unroll
            for (int mt = 0; mt < 2; mt++) {
                int r = wm * 32 + mt * 16 + rl;
                uint32_t base = Ab + (uint32_t)r * 128;
                int cH = 2 * g + kc;
                LDSM_X4(aH[mt], base + (uint32_t)((cH ^ (r & 7)) << 4));
                LDSM_X4(aL[mt], base + (uint32_t)(((cH + 4) ^ (r & 7)) << 4));
            }
            uint32_t bH[8][2], bL[8][2];
#pragma unroll
            for (int t = 0; t < 4; t++) {
                int r = wn * 64 + t * 16 + rl;
                uint32_t base = Bb + (uint32_t)r * 128;
                int cH = 2 * g + kc;
                uint32_t q[4];
                LDSM_X4(q, base + (uint32_t)((cH ^ (r & 7)) << 4));
                bH[2*t][0] = q[0]; bH[2*t+1][0] = q[1]; bH[2*t][1] = q[2]; bH[2*t+1][1] = q[3];
                LDSM_X4(q, base + (uint32_t)(((cH + 4) ^ (r & 7)) << 4));
                bL[2*t][0] = q[0]; bL[2*t+1][0] = q[1]; bL[2*t][1] = q[2]; bL[2*t+1][1] = q[3];
            }
#pragma unroll
            for (int mt = 0; mt < 2; mt++)
#pragma unroll
                for (int nt = 0; nt < 8; nt++) {
                    MMA_F16(acc[mt][nt], aH[mt], bH[nt]);
                    MMA_F16(acc[mt][nt], aH[mt], bL[nt]);
                    MMA_F16(acc[mt][nt], aL[mt], bH[nt]);
                }
        }
        if (s + 1 < NS) STA((s + 1) & 1);
        CP_WAIT0();
        __syncthreads();
    }

    // ---- epilogue
#pragma unroll
    for (int mt = 0; mt < 2; mt++) {
        int mb = m0 + wm * 32 + mt * 16 + (lane >> 2);
#pragma unroll
        for (int nt = 0; nt < 8; nt++) {
            int ocb = n0 + wn * 64 + nt * 8 + ((lane & 3) << 1);
#pragma unroll
            for (int h = 0; h < 2; h++) {
                int m = mb + h * 8;
#pragma unroll
                for (int q = 0; q < 2; q++) {
                    int oc = ocb + q;
                    float v = acc[mt][nt][h * 2 + q] * SINV + __ldg(bias + oc);
                    size_t ob;
                    if (MODE == 1) {
                        int y = m >> 5, x = m & 31;
                        ob = ((size_t)(b * Cout + oc)) * 4096 + (size_t)(2*y + ry) * 64 + (2*x + rx);
                    } else {
                        ob = ((size_t)b * Cout + oc) * 1024 + m;
                    }
                    if (ADDRES) v += res[ob];
                    if (ROUT) v = fmaxf(v, 0.f);
                    if (OUTF) outF[ob] = v;
                    if (OUTS) outS[ob] = splitpack(fmaxf(v, 0.f) * SAN);
                }
            }
        }
    }
}

// ================= fp32 implicit-GEMM conv (small layers) =================
#define FMA16S \
    acc[0][0] += bv.x*a.x; acc[0][1] += bv.x*a.y; acc[0][2] += bv.x*a.z; acc[0][3] += bv.x*a.w; \
    acc[1][0] += bv.y*a.x; acc[1][1] += bv.y*a.y; acc[1][2] += bv.y*a.z; acc[1][3] += bv.y*a.w; \
    acc[2][0] += bv.z*a.x; acc[2][1] += bv.z*a.y; acc[2][2] += bv.z*a.z; acc[2][3] += bv.z*a.w; \
    acc[3][0] += bv.w*a.x; acc[3][1] += bv.w*a.y; acc[3][2] += bv.w*a.z; acc[3][3] += bv.w*a.w;

template<int KH, int KW, int STR, int PAD, int OW, int RIN, int ROUT, int ADDRES, int OUTS>
__global__ __launch_bounds__(256) void conv_k(
    const float* __restrict__ in, const float* __restrict__ wT,
    const float* __restrict__ bias, const float* __restrict__ res,
    float* __restrict__ out, uint32_t* __restrict__ outS,
    int Cin, int IH, int IW, int MIMG, int Cout, float SAN)
{
    constexpr int T = KH * KW;
    const int K  = Cin * T;
    const int b  = blockIdx.z;
    const int m0 = blockIdx.x * 64;
    const int n0 = blockIdx.y * 64;
    __shared__ float As[16][64];
    __shared__ float Bs[16][64];
    const int tid = threadIdx.x;
    const int lm = tid & 63, lk = tid >> 6;
    const int mi = (tid & 15) << 2, ni = (tid >> 4) << 2;

    const int am = m0 + lm;
    const int ay = am / OW, ax = am % OW;
    const int ybase = ay * STR - PAD, xbase = ax * STR - PAD;
    const float* inb = in + (size_t)b * Cin * IH * IW;

    float acc[4][4] = {};
    for (int k0 = 0; k0 < K; k0 += 16) {
#pragma unroll
        for (int i = 0; i < 4; i++) {
            int k   = k0 + lk + i * 4;
            int ic  = k / T;
            int tap = k - ic * T;
            int ky  = tap / KW;
            int kx  = tap - ky * KW;
            int iy = ybase + ky, ix = xbase + kx;
            float v = 0.f;
            if ((unsigned)iy < (unsigned)IH && (unsigned)ix < (unsigned)IW)
                v = inb[(size_t)ic * IH * IW + iy * IW + ix];
            if (RIN) v = fmaxf(v, 0.f);
            As[lk + i * 4][lm] = v;
            Bs[lk + i * 4][lm] = wT[(size_t)k * Cout + n0 + lm];
        }
        __syncthreads();
#pragma unroll
        for (int kk = 0; kk < 16; kk++) {
            float4 a  = *(const float4*)&As[kk][mi];
            float4 bv = *(const float4*)&Bs[kk][ni];
            FMA16S
        }
        __syncthreads();
    }
    const int m = m0 + mi;
#pragma unroll
    for (int i = 0; i < 4; i++) {
        int oc = n0 + ni + i;
        size_t ob = ((size_t)b * Cout + oc) * MIMG + m;
        float bb = bias[oc];
        float4 r;
        r.x = acc[i][0] + bb; r.y = acc[i][1] + bb;
        r.z = acc[i][2] + bb; r.w = acc[i][3] + bb;
        if (ADDRES) {
            float4 rv = *(const float4*)&res[ob];
            r.x += rv.x; r.y += rv.y; r.z += rv.z; r.w += rv.w;
        }
        if (ROUT) {
            r.x = fmaxf(r.x, 0.f); r.y = fmaxf(r.y, 0.f);
            r.z = fmaxf(r.z, 0.f); r.w = fmaxf(r.w, 0.f);
        }
        if (OUTS) {
            uint4 u;
            u.x = splitpack(fmaxf(r.x, 0.f) * SAN);
            u.y = splitpack(fmaxf(r.y, 0.f) * SAN);
            u.z = splitpack(fmaxf(r.z, 0.f) * SAN);
            u.w = splitpack(fmaxf(r.w, 0.f) * SAN);
            *(uint4*)&outS[ob] = u;
        } else {
            *(float4*)&out[ob] = r;
        }
    }
}

// ================= t2 (256 -> 3, 64x64 -> 128x128) + sigmoid =================
__global__ __launch_bounds__(256) void t2_k(const float* __restrict__ w,
                                            const float* __restrict__ bias,
                                            float* __restrict__ out)
{
    const int cls = blockIdx.z, b = blockIdx.y;
    const int ry = cls >> 1, rx = cls & 1;
    const int oy0 = ry ? 1 : 0, oy1 = ry ? 0 : -1;
    const int ox1 = rx ? 0 : -1;
    __shared__ float ws[3072];
    for (int i = threadIdx.x; i < 3072; i += 256) {
        int ic = i / 12, r = i - ic * 12;
        int t = r / 3, oc = r - t * 3;
        int a = t >> 1, bb = t & 1;
        int ky = ry ? (a ? 2 : 0) : (a ? 3 : 1);
        int kx = rx ? (bb ? 2 : 0) : (bb ? 3 : 1);
        ws[i] = w[((size_t)(ic * 3 + oc)) * 16 + ky * 4 + kx];
    }
    __syncthreads();
    const int t = blockIdx.x * 256 + threadIdx.x;
    const int yy = t >> 4;
    const int xg = (t & 15) << 2;
    const int basex = xg + ox1;
    const float* inb = g_d1 + (size_t)b * 256 * 4096;
    float acc[4][3] = {};
    for (int ic = 0; ic < 256; ic++) {
        const float* ip = inb + ic * 4096;
        float v[2][5];
#pragma unroll
        for (int a = 0; a < 2; a++) {
            int iy = yy + (a ? oy1 : oy0);
            bool okr = (unsigned)iy < 64u;
#pragma unroll
            for (int q = 0; q < 5; q++) {
                int ix = basex + q;
                v[a][q] = (okr && (unsigned)ix < 64u) ? ip[iy * 64 + ix] : 0.f;
            }
        }
        const float* wr = &ws[ic * 12];
#pragma unroll
        for (int p = 0; p < 4; p++)
#pragma unroll
            for (int bb2 = 0; bb2 < 2; bb2++) {
#pragma unroll
                for (int a = 0; a < 2; a++) {
                    float val = v[a][p + (bb2 ? 0 : 1)];
                    int ti = a * 2 + bb2;
                    acc[p][0] += val * wr[ti * 3 + 0];
                    acc[p][1] += val * wr[ti * 3 + 1];
                    acc[p][2] += val * wr[ti * 3 + 2];
                }
            }
    }
#pragma unroll
    for (int p = 0; p < 4; p++) {
        int oy = 2 * yy + ry, ox = 2 * (xg + p) + rx;
#pragma unroll
        for (int oc = 0; oc < 3; oc++) {
            float vv = acc[p][oc] + bias[oc];
            out[((size_t)(b * 3 + oc) * 128 + oy) * 128 + ox] = 1.f / (1.f + __expf(-vv));
        }
    }
}

// ================= VQ =================
__global__ __launch_bounds__(256) void vq_k(const float* __restrict__ cb)
{
    const int n = blockIdx.x * 256 + threadIdx.x;
    const int b = n >> 10, s = n & 1023;
    const float* zp = g_ze + (size_t)b * 64 * 1024 + s;
    float z[64];
#pragma unroll
    for (int c = 0; c < 64; c++) z[c] = zp[(size_t)c * 1024];
    float z0 = 0, z1 = 0, z2a = 0, z3 = 0;
#pragma unroll
    for (int c = 0; c < 64; c += 4) {
        z0 += z[c]*z[c]; z1 += z[c+1]*z[c+1]; z2a += z[c+2]*z[c+2]; z3 += z[c+3]*z[c+3];
    }
    const float zn = (z0 + z1) + (z2a + z3);
    __shared__ float cbs[4096];
    float best = 3.4e38f; int bid = 0;
    for (int c0 = 0; c0 < 512; c0 += 64) {
        __syncthreads();
#pragma unroll
        for (int i = 0; i < 16; i++)
            cbs[threadIdx.x + i * 256] = cb[(size_t)c0 * 64 + threadIdx.x + i * 256];
        __syncthreads();
        for (int k = 0; k < 64; k++) {
            const float* cr = &cbs[k * 64];
            float d0 = 0, d1 = 0, d2 = 0, d3 = 0;
#pragma unroll
            for (int c = 0; c < 64; c += 4) {
                d0 += z[c]*cr[c]; d1 += z[c+1]*cr[c+1]; d2 += z[c+2]*cr[c+2]; d3 += z[c+3]*cr[c+3];
            }
            float dot = (d0 + d1) + (d2 + d3);
            float score = (zn - 2.0f * dot) + g_cbn[c0 + k];
            if (score < best) { best = score; bid = c0 + k; }
        }
    }
    g_ids[n] = bid;
    const float* code = cb + (size_t)bid * 64;
    float* ep = g_ek + (size_t)b * 64 * 1024 + s;
#pragma unroll
    for (int c = 0; c < 64; c++) ep[(size_t)c * 1024] = code[c];
}

// ================= pack tuple tail =================
__global__ void pack_k(float* __restrict__ out, int out_size)
{
    int i = blockIdx.x * 256 + threadIdx.x;
    if (i < 524288) {
        int o = 393216 + i;
        if (o < out_size) out[o] = g_ze[i];
    } else if (i < 1048576) {
        int j = i - 524288;
        int o = 917504 + j;
        if (o < out_size) out[o] = g_ek[j];
    } else if (i < 1056768) {
        int j = i - 1048576;
        int o = 1441792 + j;
        if (o < out_size) out[o] = (float)g_ids[j];
    }
}

// ================= launch =================
static constexpr int SMEM_TC = 65536 + 256;

extern "C" void kernel_launch(void* const* d_in, const int* in_sizes, int n_in,
                              void* d_out, int out_size)
{
    const float* x     = (const float*)d_in[0];
    const float* c1_w  = (const float*)d_in[1];
    const float* c1_b  = (const float*)d_in[2];
    const float* c2_w  = (const float*)d_in[3];
    const float* c2_b  = (const float*)d_in[4];
    const float* r0_w3 = (const float*)d_in[5];
    const float* r0_b3 = (const float*)d_in[6];
    const float* r0_w1 = (const float*)d_in[7];
    const float* r0_b1 = (const float*)d_in[8];
    const float* r1_w3 = (const float*)d_in[9];
    const float* r1_b3 = (const float*)d_in[10];
    const float* r1_w1 = (const float*)d_in[11];
    const float* r1_b1 = (const float*)d_in[12];
    const float* toz_w = (const float*)d_in[13];
    const float* toz_b = (const float*)d_in[14];
    const float* cb    = (const float*)d_in[15];
    const float* fz_w  = (const float*)d_in[16];
    const float* fz_b  = (const float*)d_in[17];
    const float* t1_w  = (const float*)d_in[18];
    const float* t1_b  = (const float*)d_in[19];
    const float* t2_w  = (const float*)d_in[20];
    const float* t2_b  = (const float*)d_in[21];
    float* out = (float*)d_out;

    void* p;
#define GETF(var, sym) cudaGetSymbolAddress(&p, sym); float* var = (float*)p;
#define GETU(var, sym) cudaGetSymbolAddress(&p, sym); uint32_t* var = (uint32_t*)p;
    GETF(h2p,  g_h2)   GETF(zep,  g_ze)   GETF(ekp,  g_ek)   GETF(d1p,  g_d1)
    GETF(wc1,  g_wc1)  GETF(wtoz, g_wtoz) GETF(wfz,  g_wfz)
    GETU(h1s,  g_h1s)  GETU(acts, g_acts) GETU(rs,   g_rs)   GETU(d0s,  g_d0s)
    GETU(wc2s, g_wc2s) GETU(wr03s,g_wr03s) GETU(wr01s,g_wr01s)
    GETU(wr13s,g_wr13s) GETU(wr11s,g_wr11s) GETU(wt1s, g_wt1s)
#undef GETF
#undef GETU

    // tconv instantiations
    auto* kc2  = tconv<0, 16, 4, 2, 1, 64, 64, 1, 1, 0, 1>;
    auto* kr3  = tconv<0,  9, 3, 1, 1, 32, 32, 0, 1, 0, 0>;
    auto* kr1a = tconv<0,  1, 1, 1, 0, 32, 32, 1, 1, 1, 0>;
    auto* kr1b = tconv<0,  1, 1, 1, 0, 32, 32, 1, 0, 1, 0>;
    auto* kt1  = tconv<1,  4, 1, 1, 0, 32, 32, 1, 0, 0, 1>;
    cudaFuncSetAttribute(kc2,  cudaFuncAttributeMaxDynamicSharedMemorySize, SMEM_TC);
    cudaFuncSetAttribute(kr3,  cudaFuncAttributeMaxDynamicSharedMemorySize, SMEM_TC);
    cudaFuncSetAttribute(kr1a, cudaFuncAttributeMaxDynamicSharedMemorySize, SMEM_TC);
    cudaFuncSetAttribute(kr1b, cudaFuncAttributeMaxDynamicSharedMemorySize, SMEM_TC);
    cudaFuncSetAttribute(kt1,  cudaFuncAttributeMaxDynamicSharedMemorySize, SMEM_TC);

    const float SA = 256.f, SW = 1024.f;
    const float SI  = 1.f / (256.f * 1024.f);
    const float SAT = 16384.f, SIT = 1.f / (16384.f * 1024.f);

    // weight prep
    wtrans<<<(48*256 + 255) / 256, 256>>>(c1_w,  wc1,  256, 48);
    wtrans<<<(256*64)  / 256, 256>>>(toz_w, wtoz, 64,  256);
    wtrans<<<(64*256)  / 256, 256>>>(fz_w,  wfz,  256, 64);
    wsplit<<<(256*4096) / 256, 256>>>(c2_w,  wc2s,  4096, SW);
    wsplit<<<(256*2304) / 256, 256>>>(r0_w3, wr03s, 2304, SW);
    wsplit<<<(256*256)  / 256, 256>>>(r0_w1, wr01s, 256,  SW);
    wsplit<<<(256*2304) / 256, 256>>>(r1_w3, wr13s, 2304, SW);
    wsplit<<<(256*256)  / 256, 256>>>(r1_w1, wr11s, 256,  SW);
    wt1split<<<(4*256*1024) / 256, 256>>>(t1_w, wt1s, SW);
    cbnorm_k<<<8, 64>>>(cb);

    // encoder
    conv_k<4,4,2,1,64,0,1,0,1><<<dim3(64,4,8), 256>>>(
        x, wc1, c1_b, nullptr, nullptr, h1s, 3, 128, 128, 4096, 256, SA);
    kc2 <<<dim3(8,2,8),  256, SMEM_TC>>>(h1s,  wc2s,  c2_b,  nullptr, h2p, acts, 4096, 256, SI, SA);
    kr3 <<<dim3(8,2,8),  256, SMEM_TC>>>(acts, wr03s, r0_b3, nullptr, nullptr, rs, 2304, 256, SI, SA);
    kr1a<<<dim3(8,2,8),  256, SMEM_TC>>>(rs,   wr01s, r0_b1, h2p,     h2p, acts, 256,  256, SI, SA);
    kr3 <<<dim3(8,2,8),  256, SMEM_TC>>>(acts, wr13s, r1_b3, nullptr, nullptr, rs, 2304, 256, SI, SA);
    kr1b<<<dim3(8,2,8),  256, SMEM_TC>>>(rs,   wr11s, r1_b1, h2p,     h2p, nullptr, 256, 256, SI, 0.f);
    conv_k<1,1,1,0,32,0,0,0,0><<<dim3(16,1,8), 256>>>(
        h2p, wtoz, toz_b, nullptr, zep, nullptr, 256, 32, 32, 1024, 64, 0.f);

    // vector quantization
    vq_k<<<32, 256>>>(cb);

    // decoder
    conv_k<1,1,1,0,32,0,1,0,1><<<dim3(16,4,8), 256>>>(
        ekp, wfz, fz_b, nullptr, nullptr, d0s, 64, 32, 32, 1024, 256, SAT);
    kt1<<<dim3(8,2,32), 256, SMEM_TC>>>(d0s, wt1s, t1_b, nullptr, d1p, nullptr, 1024, 256, SIT, 0.f);
    t2_k<<<dim3(4,8,4), 256>>>(t2_w, t2_b, out);

    // pack z_e / e_k / ids
    pack_k<<<4128, 256>>>(out, out_size);
}

// round 9
// speedup vs baseline: 2.3954x; 1.2386x over previous
#include <cuda_runtime.h>
#include <cuda_fp16.h>
#include <cstdint>
#include <math.h>

// ================= static shapes =================
// B=8, HID=256, ZC=64, K=512
__device__ float    g_h2[8*256*32*32];
__device__ float    g_ze[8*64*32*32];
__device__ float    g_ek[8*64*32*32];
__device__ float    g_d1[8*256*64*64];
__device__ int      g_ids[8192];
__device__ float    g_cbn[512];
__device__ float    g_wtoz[256*64];
__device__ float    g_wfz [64*256];
__device__ float    g_vqs[4*8192];
__device__ int      g_vqi[4*8192];
// split activations (u32 = hi16<<16 | lo16), pre-scaled, post-relu
__device__ uint32_t g_xs  [8*3*128*128];
__device__ uint32_t g_h1s [8*256*64*64];
__device__ uint32_t g_acts[8*256*32*32];
__device__ uint32_t g_rs  [8*256*32*32];
__device__ uint32_t g_d0s [8*256*32*32];
// split weights, per-stage chunk layout: [(s*256+oc)*8+c]*4+w ; c<4 hi, c>=4 lo
__device__ uint32_t g_wc1s [256*64];
__device__ uint32_t g_wc2s [256*4096];
__device__ uint32_t g_wr03s[256*2304];
__device__ uint32_t g_wr01s[256*256];
__device__ uint32_t g_wr13s[256*2304];
__device__ uint32_t g_wr11s[256*256];
__device__ uint32_t g_wt1s [4*256*1024];

// ================= helpers =================
__device__ __forceinline__ uint32_t smem_u32(const void* p) {
    uint32_t a;
    asm("{ .reg .u64 t; cvta.to.shared.u64 t, %1; cvt.u32.u64 %0, t; }" : "=r"(a) : "l"(p));
    return a;
}
#define LDSM_X4(r, addr) \
    asm volatile("ldmatrix.sync.aligned.m8n8.x4.shared.b16 {%0,%1,%2,%3}, [%4];" \
        : "=r"((r)[0]), "=r"((r)[1]), "=r"((r)[2]), "=r"((r)[3]) : "r"(addr))
#define MMA_F16(d, a, b) \
    asm volatile("mma.sync.aligned.m16n8k16.row.col.f32.f16.f16.f32 " \
        "{%0,%1,%2,%3}, {%4,%5,%6,%7}, {%8,%9}, {%0,%1,%2,%3};" \
        : "+f"((d)[0]), "+f"((d)[1]), "+f"((d)[2]), "+f"((d)[3]) \
        : "r"((a)[0]), "r"((a)[1]), "r"((a)[2]), "r"((a)[3]), "r"((b)[0]), "r"((b)[1]))
#define CP_ASYNC16(dst, src) \
    asm volatile("cp.async.cg.shared.global [%0], [%1], 16;" :: "r"(dst), "l"(src) : "memory")
#define CP_COMMIT()  asm volatile("cp.async.commit_group;" ::: "memory")
#define CP_WAIT0()   asm volatile("cp.async.wait_group 0;" ::: "memory")

__device__ __forceinline__ uint32_t splitpack(float v) {
    unsigned short h = __half_as_ushort(__float2half_rn(v));
    float r = v - __half2float(__ushort_as_half(h));
    unsigned short l = __half_as_ushort(__float2half_rn(r));
    return ((uint32_t)h << 16) | (uint32_t)l;
}

// ================= prep kernels =================
__global__ void wtrans(const float* __restrict__ src, float* __restrict__ dst,
                       int Cout, int K) {
    int i = blockIdx.x * 256 + threadIdx.x;
    if (i >= Cout * K) return;
    int k = i / Cout, oc = i - k * Cout;
    dst[i] = src[(size_t)oc * K + k];
}
__global__ void xsplit(const float* __restrict__ x, uint32_t* __restrict__ dst, float SA) {
    int i = blockIdx.x * 256 + threadIdx.x;
    if (i >= 8*3*16384) return;
    dst[i] = splitpack(x[i] * SA);
}
// split weights into per-stage chunk layout (Ksrc real, Kpad padded with zeros)
__global__ void wsplit(const float* __restrict__ src, uint32_t* __restrict__ dst,
                       int Ksrc, int Kpad, float SW) {
    int u = blockIdx.x * 256 + threadIdx.x;
    if (u >= 256 * Kpad) return;
    int w = u & 3, c = (u >> 2) & 7, oc = (u >> 5) & 255, s = u >> 13;
    int kb = 32 * s + 8 * (c & 3) + 2 * w;
    float v0 = (kb     < Ksrc) ? src[(size_t)oc * Ksrc + kb]     * SW : 0.f;
    float v1 = (kb + 1 < Ksrc) ? src[(size_t)oc * Ksrc + kb + 1] * SW : 0.f;
    unsigned short h0 = __half_as_ushort(__float2half_rn(v0));
    unsigned short h1 = __half_as_ushort(__float2half_rn(v1));
    uint32_t val;
    if (c < 4) val = (uint32_t)h0 | ((uint32_t)h1 << 16);
    else {
        unsigned short l0 = __half_as_ushort(__float2half_rn(v0 - __half2float(__ushort_as_half(h0))));
        unsigned short l1 = __half_as_ushort(__float2half_rn(v1 - __half2float(__ushort_as_half(h1))));
        val = (uint32_t)l0 | ((uint32_t)l1 << 16);
    }
    dst[u] = val;
}
__global__ void wt1split(const float* __restrict__ w, uint32_t* __restrict__ dst, float SW) {
    int u = blockIdx.x * 256 + threadIdx.x;   // 4*256*1024
    int cls = u >> 18;
    int r = u & 262143;
    int ww = r & 3, c = (r >> 2) & 7, oc = (r >> 5) & 255, s = r >> 13;
    int ry = cls >> 1, rx = cls & 1;
    int kb = 32 * s + 8 * (c & 3) + 2 * ww;
    float v[2];
#pragma unroll
    for (int j = 0; j < 2; j++) {
        int k = kb + j;
        int ic = k >> 2, t = k & 3;
        int a = t >> 1, bb = t & 1;
        int ky = ry ? (a ? 2 : 0) : (a ? 3 : 1);
        int kx = rx ? (bb ? 2 : 0) : (bb ? 3 : 1);
        v[j] = w[((size_t)(ic * 256 + oc)) * 16 + ky * 4 + kx] * SW;
    }
    unsigned short h0 = __half_as_ushort(__float2half_rn(v[0]));
    unsigned short h1 = __half_as_ushort(__float2half_rn(v[1]));
    uint32_t val;
    if (c < 4) val = (uint32_t)h0 | ((uint32_t)h1 << 16);
    else {
        unsigned short l0 = __half_as_ushort(__float2half_rn(v[0] - __half2float(__ushort_as_half(h0))));
        unsigned short l1 = __half_as_ushort(__float2half_rn(v[1] - __half2float(__ushort_as_half(h1))));
        val = (uint32_t)l0 | ((uint32_t)l1 << 16);
    }
    dst[u] = val;
}
__global__ void cbnorm_k(const float* __restrict__ cb) {
    int k = blockIdx.x * 64 + threadIdx.x;
    if (k >= 512) return;
    const float* r = cb + (size_t)k * 64;
    float s0 = 0, s1 = 0, s2 = 0, s3 = 0;
#pragma unroll
    for (int c = 0; c < 64; c += 4) {
        s0 += r[c]*r[c]; s1 += r[c+1]*r[c+1]; s2 += r[c+2]*r[c+2]; s3 += r[c+3]*r[c+3];
    }
    g_cbn[k] = (s0 + s1) + (s2 + s3);
}

// ================= tensor-core conv (mma.sync fp16-split) =================
// A: gather pre-split u32 activations; B: cp.async pre-split weights.
// MODE 0: standard conv. MODE 1: t1 parity-class GEMM (scatter epilogue).
// NT: 3-term (AhBh+AhBl+AlBh) or 2-term (AhBh+AhBl).
template<int MODE, int T, int KW, int STR, int PAD, int IH, int IW, int OWB,
         int MIMG, int CINOVR, int NT, int OUTF, int OUTS, int ADDRES, int ROUT>
__global__ __launch_bounds__(256) void tconv(
    const uint32_t* __restrict__ inS, const uint32_t* __restrict__ wS,
    const float* __restrict__ bias, const float* __restrict__ res,
    float* __restrict__ outF, uint32_t* __restrict__ outS,
    int K, int Cout, float SINV, float SAN)
{
    extern __shared__ __align__(128) char smem[];
    const uint32_t sb0 = (smem_u32(smem) + 127) & ~127u;
    const int tid = threadIdx.x, lane = tid & 31, wid = tid >> 5;
    const int zi = blockIdx.z;
    int b, ry = 0, rx = 0, oy0 = 0, oy1 = 0, ox0 = 0, ox1 = 0;
    const uint32_t* wg = wS;
    if (MODE == 1) {
        b = zi >> 2; int cls = zi & 3;
        ry = cls >> 1; rx = cls & 1;
        oy0 = ry ? 1 : 0; oy1 = ry ? 0 : -1;
        ox0 = rx ? 1 : 0; ox1 = rx ? 0 : -1;
        wg = wS + (size_t)cls * 262144;
    } else b = zi;
    const int m0 = blockIdx.x * 128;
    const int n0 = blockIdx.y * 128;
    const int Cin = CINOVR ? CINOVR : ((MODE == 1) ? 256 : K / T);
    const uint32_t* inb = inS + (size_t)b * Cin * IH * IW;

    uint32_t stA[8][2];

    auto GA = [&](int s) {
        const int k0 = s << 5;
#pragma unroll
        for (int i = 0; i < 8; i++) {
            int kp  = (lane >> 3) | ((i & 3) << 2);
            int row = (lane & 7) | (wid << 3) | ((i >> 2) << 6);
            int m = m0 + row;
            uint32_t e0, e1;
            if (MODE == 1) {
                int y = m >> 5, x = m & 31;
#pragma unroll
                for (int j = 0; j < 2; j++) {
                    int k = k0 + 2 * kp + j;
                    int ic = k >> 2, t = k & 3;
                    int iy = y + ((t & 2) ? oy1 : oy0);
                    int ix = x + ((t & 1) ? ox1 : ox0);
                    uint32_t e = 0;
                    if ((unsigned)iy < 32u && (unsigned)ix < 32u)
                        e = inb[ic * 1024 + iy * 32 + ix];
                    (j ? e1 : e0) = e;
                }
            } else if (T == 1) {
                int k = k0 + 2 * kp;
                e0 = inb[(size_t)k * 1024 + m];
                e1 = inb[(size_t)(k + 1) * 1024 + m];
            } else {
                int ay = m >> OWB, ax = m & ((1 << OWB) - 1);
                int yb = ay * STR - PAD, xb = ax * STR - PAD;
#pragma unroll
                for (int j = 0; j < 2; j++) {
                    int k = k0 + 2 * kp + j;
                    int ic = k / T, tap = k - ic * T;
                    int ky = tap / KW, kx = tap - ky * KW;
                    int iy = yb + ky, ix = xb + kx;
                    uint32_t e = 0;
                    bool okc = (!CINOVR) || (ic < Cin);
                    if (okc && (unsigned)iy < (unsigned)IH && (unsigned)ix < (unsigned)IW)
                        e = inb[(size_t)ic * (IH * IW) + iy * IW + ix];
                    (j ? e1 : e0) = e;
                }
            }
            stA[i][0] = __byte_perm(e0, e1, 0x7632);  // hi pair
            stA[i][1] = __byte_perm(e0, e1, 0x5410);  // lo pair
        }
    };
    auto STA = [&](int bufid) {
        const uint32_t Ab = sb0 + bufid * 32768;
#pragma unroll
        for (int i = 0; i < 8; i++) {
            int kp  = (lane >> 3) | ((i & 3) << 2);
            int row = (lane & 7) | (wid << 3) | ((i >> 2) << 6);
            uint32_t c = kp >> 2, w = kp & 3;
            uint32_t offH = (uint32_t)row * 128 + ((c ^ (row & 7)) << 4) + (w << 2);
            uint32_t offL = (uint32_t)row * 128 + (((c + 4) ^ (row & 7)) << 4) + (w << 2);
            asm volatile("st.shared.b32 [%0], %1;" :: "r"(Ab + offH), "r"(stA[i][0]) : "memory");
            if (NT == 3)
                asm volatile("st.shared.b32 [%0], %1;" :: "r"(Ab + offL), "r"(stA[i][1]) : "memory");
        }
    };
    auto GB = [&](int s, int bufid) {
        const uint32_t Bb = sb0 + bufid * 32768 + 16384;
#pragma unroll
        for (int i = 0; i < 4; i++) {
            int q = tid + i * 256;
            int r = q >> 3, cc = q & 7;
            const uint32_t* src = wg + (((size_t)s * 256 + n0 + r) * 8 + cc) * 4;
            uint32_t dst = Bb + (uint32_t)r * 128 + ((uint32_t)(cc ^ (r & 7)) << 4);
            CP_ASYNC16(dst, src);
        }
        CP_COMMIT();
    };

    const int wm = wid & 3, wn = wid >> 2;
    float acc[2][8][4] = {};
    const int rl = lane & 15, kc = lane >> 4;

    const int NS = K >> 5;
    GB(0, 0); GA(0); STA(0);
    CP_WAIT0();
    __syncthreads();
    for (int s = 0; s < NS; s++) {
        if (s + 1 < NS) { GB(s + 1, (s + 1) & 1); GA(s + 1); }
        const uint32_t Ab = sb0 + (s & 1) * 32768, Bb = Ab + 16384;
#pragma unroll
        for (int g = 0; g < 2; g++) {
            uint32_t aH[2][4], aL[2][4];
#pragma unroll
            for (int mt = 0; mt < 2; mt++) {
                int r = wm * 32 + mt * 16 + rl;
                uint32_t base = Ab + (uint32_t)r * 128;
                int cH = 2 * g + kc;
                LDSM_X4(aH[mt], base + (uint32_t)((cH ^ (r & 7)) << 4));
                if (NT == 3)
                    LDSM_X4(aL[mt], base + (uint32_t)(((cH + 4) ^ (r & 7)) << 4));
            }
            uint32_t bH[8][2], bL[8][2];
#pragma unroll
            for (int t = 0; t < 4; t++) {
                int r = wn * 64 + t * 16 + rl;
                uint32_t base = Bb + (uint32_t)r * 128;
                int cH = 2 * g + kc;
                uint32_t q[4];
                LDSM_X4(q, base + (uint32_t)((cH ^ (r & 7)) << 4));
                bH[2*t][0] = q[0]; bH[2*t+1][0] = q[1]; bH[2*t][1] = q[2]; bH[2*t+1][1] = q[3];
                LDSM_X4(q, base + (uint32_t)(((cH + 4) ^ (r & 7)) << 4));
                bL[2*t][0] = q[0]; bL[2*t+1][0] = q[1]; bL[2*t][1] = q[2]; bL[2*t+1][1] = q[3];
            }
#pragma unroll
            for (int mt = 0; mt < 2; mt++)
#pragma unroll
                for (int nt = 0; nt < 8; nt++) {
                    MMA_F16(acc[mt][nt], aH[mt], bH[nt]);
                    MMA_F16(acc[mt][nt], aH[mt], bL[nt]);
                    if (NT == 3) MMA_F16(acc[mt][nt], aL[mt], bH[nt]);
                }
        }
        if (s + 1 < NS) STA((s + 1) & 1);
        CP_WAIT0();
        __syncthreads();
    }

    // ---- epilogue
#pragma unroll
    for (int mt = 0; mt < 2; mt++) {
        int mb = m0 + wm * 32 + mt * 16 + (lane >> 2);
#pragma unroll
        for (int nt = 0; nt < 8; nt++) {
            int ocb = n0 + wn * 64 + nt * 8 + ((lane & 3) << 1);
#pragma unroll
            for (int h = 0; h < 2; h++) {
                int m = mb + h * 8;
#pragma unroll
                for (int q = 0; q < 2; q++) {
                    int oc = ocb + q;
                    float v = acc[mt][nt][h * 2 + q] * SINV + __ldg(bias + oc);
                    size_t ob;
                    if (MODE == 1) {
                        int y = m >> 5, x = m & 31;
                        ob = ((size_t)(b * Cout + oc)) * 4096 + (size_t)(2*y + ry) * 64 + (2*x + rx);
                    } else {
                        ob = ((size_t)b * Cout + oc) * MIMG + m;
                    }
                    if (ADDRES) v += res[ob];
                    if (ROUT) v = fmaxf(v, 0.f);
                    if (OUTF) outF[ob] = v;
                    if (OUTS) outS[ob] = splitpack(fmaxf(v, 0.f) * SAN);
                }
            }
        }
    }
}

// ================= fp32 implicit-GEMM conv (toz / fz) =================
#define FMA16S \
    acc[0][0] += bv.x*a.x; acc[0][1] += bv.x*a.y; acc[0][2] += bv.x*a.z; acc[0][3] += bv.x*a.w; \
    acc[1][0] += bv.y*a.x; acc[1][1] += bv.y*a.y; acc[1][2] += bv.y*a.z; acc[1][3] += bv.y*a.w; \
    acc[2][0] += bv.z*a.x; acc[2][1] += bv.z*a.y; acc[2][2] += bv.z*a.z; acc[2][3] += bv.z*a.w; \
    acc[3][0] += bv.w*a.x; acc[3][1] += bv.w*a.y; acc[3][2] += bv.w*a.z; acc[3][3] += bv.w*a.w;

template<int ROUT, int OUTS>
__global__ __launch_bounds__(256) void conv1x1_k(
    const float* __restrict__ in, const float* __restrict__ wT,
    const float* __restrict__ bias,
    float* __restrict__ out, uint32_t* __restrict__ outS,
    int Cin, int Cout, float SAN)
{
    const int K = Cin;
    const int b  = blockIdx.z;
    const int m0 = blockIdx.x * 64;
    const int n0 = blockIdx.y * 64;
    __shared__ float As[16][64];
    __shared__ float Bs[16][64];
    const int tid = threadIdx.x;
    const int lm = tid & 63, lk = tid >> 6;
    const int mi = (tid & 15) << 2, ni = (tid >> 4) << 2;
    const float* inb = in + (size_t)b * Cin * 1024;

    float acc[4][4] = {};
    for (int k0 = 0; k0 < K; k0 += 16) {
#pragma unroll
        for (int i = 0; i < 4; i++) {
            int k = k0 + lk + i * 4;
            As[lk + i * 4][lm] = inb[(size_t)k * 1024 + m0 + lm];
            Bs[lk + i * 4][lm] = wT[(size_t)k * Cout + n0 + lm];
        }
        __syncthreads();
#pragma unroll
        for (int kk = 0; kk < 16; kk++) {
            float4 a  = *(const float4*)&As[kk][mi];
            float4 bv = *(const float4*)&Bs[kk][ni];
            FMA16S
        }
        __syncthreads();
    }
    const int m = m0 + mi;
#pragma unroll
    for (int i = 0; i < 4; i++) {
        int oc = n0 + ni + i;
        size_t ob = ((size_t)b * Cout + oc) * 1024 + m;
        float bb = bias[oc];
        float4 r;
        r.x = acc[i][0] + bb; r.y = acc[i][1] + bb;
        r.z = acc[i][2] + bb; r.w = acc[i][3] + bb;
        if (ROUT) {
            r.x = fmaxf(r.x, 0.f); r.y = fmaxf(r.y, 0.f);
            r.z = fmaxf(r.z, 0.f); r.w = fmaxf(r.w, 0.f);
        }
        if (OUTS) {
            uint4 u;
            u.x = splitpack(fmaxf(r.x, 0.f) * SAN);
            u.y = splitpack(fmaxf(r.y, 0.f) * SAN);
            u.z = splitpack(fmaxf(r.z, 0.f) * SAN);
            u.w = splitpack(fmaxf(r.w, 0.f) * SAN);
            *(uint4*)&outS[ob] = u;
        } else {
            *(float4*)&out[ob] = r;
        }
    }
}

// ================= t2 (256 -> 3, 64x64 -> 128x128) + sigmoid =================
__global__ __launch_bounds__(128) void t2_k(const float* __restrict__ w,
                                            const float* __restrict__ bias,
                                            float* __restrict__ out)
{
    const int cls = blockIdx.z, b = blockIdx.y;
    const int ry = cls >> 1, rx = cls & 1;
    const int oy0 = ry ? 1 : 0, oy1 = ry ? 0 : -1;
    const int ox1 = rx ? 0 : -1;
    __shared__ float ws[3072];
    for (int i = threadIdx.x; i < 3072; i += 128) {
        int ic = i / 12, r = i - ic * 12;
        int t = r / 3, oc = r - t * 3;
        int a = t >> 1, bb = t & 1;
        int ky = ry ? (a ? 2 : 0) : (a ? 3 : 1);
        int kx = rx ? (bb ? 2 : 0) : (bb ? 3 : 1);
        ws[i] = w[((size_t)(ic * 3 + oc)) * 16 + ky * 4 + kx];
    }
    __syncthreads();
    const int t = blockIdx.x * 128 + threadIdx.x;   // 0..1023
    const int yy = t >> 4;
    const int xg = (t & 15) << 2;
    const int basex = xg + ox1;
    const float* inb = g_d1 + (size_t)b * 256 * 4096;
    float acc[4][3] = {};
    for (int ic = 0; ic < 256; ic++) {
        const float* ip = inb + ic * 4096;
        float v[2][5];
#pragma unroll
        for (int a = 0; a < 2; a++) {
            int iy = yy + (a ? oy1 : oy0);
            bool okr = (unsigned)iy < 64u;
#pragma unroll
            for (int q = 0; q < 5; q++) {
                int ix = basex + q;
                v[a][q] = (okr && (unsigned)ix < 64u) ? ip[iy * 64 + ix] : 0.f;
            }
        }
        const float* wr = &ws[ic * 12];
#pragma unroll
        for (int p = 0; p < 4; p++)
#pragma unroll
            for (int bb2 = 0; bb2 < 2; bb2++) {
#pragma unroll
                for (int a = 0; a < 2; a++) {
                    float val = v[a][p + (bb2 ? 0 : 1)];
                    int ti = a * 2 + bb2;
                    acc[p][0] += val * wr[ti * 3 + 0];
                    acc[p][1] += val * wr[ti * 3 + 1];
                    acc[p][2] += val * wr[ti * 3 + 2];
                }
            }
    }
#pragma unroll
    for (int p = 0; p < 4; p++) {
        int oy = 2 * yy + ry, ox = 2 * (xg + p) + rx;
#pragma unroll
        for (int oc = 0; oc < 3; oc++) {
            float vv = acc[p][oc] + bias[oc];
            out[((size_t)(b * 3 + oc) * 128 + oy) * 128 + ox] = 1.f / (1.f + __expf(-vv));
        }
    }
}

// ================= VQ (chunked argmin) =================
__global__ __launch_bounds__(256) void vq_part(const float* __restrict__ cb)
{
    const int n = blockIdx.x * 256 + threadIdx.x;   // position
    const int chunk = blockIdx.y;                   // 0..3 (128 codes each)
    const int c0base = chunk * 128;
    const int b = n >> 10, s = n & 1023;
    const float* zp = g_ze + (size_t)b * 64 * 1024 + s;
    float z[64];
#pragma unroll
    for (int c = 0; c < 64; c++) z[c] = zp[(size_t)c * 1024];
    float z0 = 0, z1 = 0, z2a = 0, z3 = 0;
#pragma unroll
    for (int c = 0; c < 64; c += 4) {
        z0 += z[c]*z[c]; z1 += z[c+1]*z[c+1]; z2a += z[c+2]*z[c+2]; z3 += z[c+3]*z[c+3];
    }
    const float zn = (z0 + z1) + (z2a + z3);
    __shared__ float cbs[8192];    // 128 codes x 64
    for (int i = threadIdx.x; i < 8192; i += 256)
        cbs[i] = cb[(size_t)c0base * 64 + i];
    __syncthreads();
    float best = 3.4e38f; int bid = 0;
    for (int k = 0; k < 128; k++) {
        const float* cr = &cbs[k * 64];
        float d0 = 0, d1 = 0, d2 = 0, d3 = 0;
#pragma unroll
        for (int c = 0; c < 64; c += 4) {
            d0 += z[c]*cr[c]; d1 += z[c+1]*cr[c+1]; d2 += z[c+2]*cr[c+2]; d3 += z[c+3]*cr[c+3];
        }
        float dot = (d0 + d1) + (d2 + d3);
        float score = (zn - 2.0f * dot) + g_cbn[c0base + k];
        if (score < best) { best = score; bid = c0base + k; }
    }
    g_vqs[chunk * 8192 + n] = best;
    g_vqi[chunk * 8192 + n] = bid;
}
__global__ __launch_bounds__(256) void vq_reduce(const float* __restrict__ cb)
{
    const int n = blockIdx.x * 256 + threadIdx.x;
    float best = g_vqs[n]; int bid = g_vqi[n];
#pragma unroll
    for (int ch = 1; ch < 4; ch++) {
        float s = g_vqs[ch * 8192 + n];
        int   i = g_vqi[ch * 8192 + n];
        if (s < best) { best = s; bid = i; }
    }
    g_ids[n] = bid;
    const int b = n >> 10, s2 = n & 1023;
    const float* code = cb + (size_t)bid * 64;
    float* ep = g_ek + (size_t)b * 64 * 1024 + s2;
#pragma unroll
    for (int c = 0; c < 64; c++) ep[(size_t)c * 1024] = code[c];
}

// ================= pack tuple tail =================
__global__ void pack_k(float* __restrict__ out, int out_size)
{
    int i = blockIdx.x * 256 + threadIdx.x;
    if (i < 524288) {
        int o = 393216 + i;
        if (o < out_size) out[o] = g_ze[i];
    } else if (i < 1048576) {
        int j = i - 524288;
        int o = 917504 + j;
        if (o < out_size) out[o] = g_ek[j];
    } else if (i < 1056768) {
        int j = i - 1048576;
        int o = 1441792 + j;
        if (o < out_size) out[o] = (float)g_ids[j];
    }
}

// ================= launch =================
static constexpr int SMEM_TC = 65536 + 256;

extern "C" void kernel_launch(void* const* d_in, const int* in_sizes, int n_in,
                              void* d_out, int out_size)
{
    const float* x     = (const float*)d_in[0];
    const float* c1_w  = (const float*)d_in[1];
    const float* c1_b  = (const float*)d_in[2];
    const float* c2_w  = (const float*)d_in[3];
    const float* c2_b  = (const float*)d_in[4];
    const float* r0_w3 = (const float*)d_in[5];
    const float* r0_b3 = (const float*)d_in[6];
    const float* r0_w1 = (const float*)d_in[7];
    const float* r0_b1 = (const float*)d_in[8];
    const float* r1_w3 = (const float*)d_in[9];
    const float* r1_b3 = (const float*)d_in[10];
    const float* r1_w1 = (const float*)d_in[11];
    const float* r1_b1 = (const float*)d_in[12];
    const float* toz_w = (const float*)d_in[13];
    const float* toz_b = (const float*)d_in[14];
    const float* cb    = (const float*)d_in[15];
    const float* fz_w  = (const float*)d_in[16];
    const float* fz_b  = (const float*)d_in[17];
    const float* t1_w  = (const float*)d_in[18];
    const float* t1_b  = (const float*)d_in[19];
    const float* t2_w  = (const float*)d_in[20];
    const float* t2_b  = (const float*)d_in[21];
    float* out = (float*)d_out;

    void* p;
#define GETF(var, sym) cudaGetSymbolAddress(&p, sym); float* var = (float*)p;
#define GETU(var, sym) cudaGetSymbolAddress(&p, sym); uint32_t* var = (uint32_t*)p;
    GETF(h2p,  g_h2)   GETF(zep,  g_ze)   GETF(ekp,  g_ek)   GETF(d1p,  g_d1)
    GETF(wtoz, g_wtoz) GETF(wfz,  g_wfz)
    GETU(xs,   g_xs)   GETU(h1s,  g_h1s)  GETU(acts, g_acts) GETU(rs,   g_rs)
    GETU(d0s,  g_d0s)
    GETU(wc1s, g_wc1s) GETU(wc2s, g_wc2s) GETU(wr03s,g_wr03s) GETU(wr01s,g_wr01s)
    GETU(wr13s,g_wr13s) GETU(wr11s,g_wr11s) GETU(wt1s, g_wt1s)
#undef GETF
#undef GETU

    // tconv instantiations
    // <MODE,T,KW,STR,PAD,IH,IW,OWB,MIMG,CINOVR,NT,OUTF,OUTS,ADDRES,ROUT>
    auto* kc1  = tconv<0,16,4,2,1,128,128,6,4096, 3, 3, 0,1,0,1>;
    auto* kc2  = tconv<0,16,4,2,1, 64, 64,5,1024, 0, 3, 1,1,0,1>;
    auto* kr3  = tconv<0, 9,3,1,1, 32, 32,5,1024, 0, 3, 0,1,0,0>;
    auto* kr1a = tconv<0, 1,1,1,0, 32, 32,5,1024, 0, 3, 1,1,1,0>;
    auto* kr1b = tconv<0, 1,1,1,0, 32, 32,5,1024, 0, 3, 1,0,1,0>;
    auto* kt1  = tconv<1, 4,1,1,0, 32, 32,5,1024, 0, 2, 1,0,0,1>;
    cudaFuncSetAttribute(kc1,  cudaFuncAttributeMaxDynamicSharedMemorySize, SMEM_TC);
    cudaFuncSetAttribute(kc2,  cudaFuncAttributeMaxDynamicSharedMemorySize, SMEM_TC);
    cudaFuncSetAttribute(kr3,  cudaFuncAttributeMaxDynamicSharedMemorySize, SMEM_TC);
    cudaFuncSetAttribute(kr1a, cudaFuncAttributeMaxDynamicSharedMemorySize, SMEM_TC);
    cudaFuncSetAttribute(kr1b, cudaFuncAttributeMaxDynamicSharedMemorySize, SMEM_TC);
    cudaFuncSetAttribute(kt1,  cudaFuncAttributeMaxDynamicSharedMemorySize, SMEM_TC);

    const float SA = 256.f, SW = 1024.f;
    const float SI  = 1.f / (256.f * 1024.f);
    const float SAT = 16384.f, SIT = 1.f / (16384.f * 1024.f);

    // --- launch order chosen so ncu (-s 5 -c 1) profiles kc2 (launch #5) ---
    xsplit<<<(8*3*16384) / 256, 256>>>(x, xs, SA);                       // 0
    wsplit<<<(256*64)   / 256, 256>>>(c1_w,  wc1s, 48, 64, SW);          // 1
    kc1<<<dim3(32,2,8), 256, SMEM_TC>>>(xs, wc1s, c1_b, nullptr,         // 2
        nullptr, h1s, 64, 256, SI, SA);
    wsplit<<<(256*4096) / 256, 256>>>(c2_w,  wc2s, 4096, 4096, SW);      // 3
    cbnorm_k<<<8, 64>>>(cb);                                             // 4
    kc2<<<dim3(8,2,8), 256, SMEM_TC>>>(h1s, wc2s, c2_b, nullptr,         // 5 <- profiled
        h2p, acts, 4096, 256, SI, SA);

    wsplit<<<(256*2304) / 256, 256>>>(r0_w3, wr03s, 2304, 2304, SW);
    kr3 <<<dim3(8,2,8), 256, SMEM_TC>>>(acts, wr03s, r0_b3, nullptr, nullptr, rs, 2304, 256, SI, SA);
    wsplit<<<(256*256)  / 256, 256>>>(r0_w1, wr01s, 256, 256, SW);
    kr1a<<<dim3(8,2,8), 256, SMEM_TC>>>(rs,   wr01s, r0_b1, h2p,     h2p, acts, 256,  256, SI, SA);
    wsplit<<<(256*2304) / 256, 256>>>(r1_w3, wr13s, 2304, 2304, SW);
    kr3 <<<dim3(8,2,8), 256, SMEM_TC>>>(acts, wr13s, r1_b3, nullptr, nullptr, rs, 2304, 256, SI, SA);
    wsplit<<<(256*256)  / 256, 256>>>(r1_w1, wr11s, 256, 256, SW);
    kr1b<<<dim3(8,2,8), 256, SMEM_TC>>>(rs,   wr11s, r1_b1, h2p,     h2p, nullptr, 256, 256, SI, 0.f);

    wtrans<<<(256*64) / 256, 256>>>(toz_w, wtoz, 64, 256);
    conv1x1_k<0,0><<<dim3(16,1,8), 256>>>(h2p, wtoz, toz_b, zep, nullptr, 256, 64, 0.f);

    // vector quantization
    vq_part<<<dim3(32,4), 256>>>(cb);
    vq_reduce<<<32, 256>>>(cb);

    // decoder
    wtrans<<<(64*256) / 256, 256>>>(fz_w, wfz, 256, 64);
    conv1x1_k<1,1><<<dim3(16,4,8), 256>>>(ekp, wfz, fz_b, nullptr, d0s, 64, 256, SAT);
    wt1split<<<(4*256*1024) / 256, 256>>>(t1_w, wt1s, SW);
    kt1<<<dim3(8,2,32), 256, SMEM_TC>>>(d0s, wt1s, t1_b, nullptr, d1p, nullptr, 1024, 256, SIT, 0.f);
    t2_k<<<dim3(8,8,4), 128>>>(t2_w, t2_b, out);

    // pack z_e / e_k / ids
    pack_k<<<4128, 256>>>(out, out_size);
}

// round 10
// speedup vs baseline: 2.6436x; 1.1036x over previous
#include <cuda_runtime.h>
#include <cuda_fp16.h>
#include <cstdint>
#include <math.h>

// ================= static shapes =================
// B=8, HID=256, ZC=64, K=512
__device__ float    g_h2[8*256*32*32];
__device__ float    g_ze[8*64*32*32];
__device__ float    g_ek[8*64*32*32];
__device__ float    g_d1[8*256*64*64];
__device__ int      g_ids[8192];
__device__ float    g_cbn[512];
__device__ float    g_wtoz[256*64];
__device__ float    g_wfz [64*256];
__device__ float    g_vqs[4*8192];
__device__ int      g_vqi[4*8192];
// padded split activations (u32 = hi16<<16 | lo16), pre-scaled, post-relu, zero halos
// xs:  [b][c(3)][131x131]  (+guard plane for padded-K reads)
// h1s: [b][ic(256)][67x67]
// acts/rs/d0s: [b][ic(256)][34x34]
__device__ uint32_t g_xs  [8*3*17161 + 17168];
__device__ uint32_t g_h1s [8*256*4489];
__device__ uint32_t g_acts[8*256*1156];
__device__ uint32_t g_rs  [8*256*1156];
__device__ uint32_t g_d0s [8*256*1156];
// split weights, per-stage chunk layout: [(s*256+oc)*8+c]*4+w ; c<4 hi, c>=4 lo
__device__ uint32_t g_wc1s [256*64];
__device__ uint32_t g_wc2s [256*4096];
__device__ uint32_t g_wr03s[256*2304];
__device__ uint32_t g_wr01s[256*256];
__device__ uint32_t g_wr13s[256*2304];
__device__ uint32_t g_wr11s[256*256];
__device__ uint32_t g_wt1s [4*256*1024];

// ================= helpers =================
__device__ __forceinline__ uint32_t smem_u32(const void* p) {
    uint32_t a;
    asm("{ .reg .u64 t; cvta.to.shared.u64 t, %1; cvt.u32.u64 %0, t; }" : "=r"(a) : "l"(p));
    return a;
}
#define LDSM_X4(r, addr) \
    asm volatile("ldmatrix.sync.aligned.m8n8.x4.shared.b16 {%0,%1,%2,%3}, [%4];" \
        : "=r"((r)[0]), "=r"((r)[1]), "=r"((r)[2]), "=r"((r)[3]) : "r"(addr))
#define MMA_F16(d, a, b) \
    asm volatile("mma.sync.aligned.m16n8k16.row.col.f32.f16.f16.f32 " \
        "{%0,%1,%2,%3}, {%4,%5,%6,%7}, {%8,%9}, {%0,%1,%2,%3};" \
        : "+f"((d)[0]), "+f"((d)[1]), "+f"((d)[2]), "+f"((d)[3]) \
        : "r"((a)[0]), "r"((a)[1]), "r"((a)[2]), "r"((a)[3]), "r"((b)[0]), "r"((b)[1]))
#define CP_ASYNC16(dst, src) \
    asm volatile("cp.async.cg.shared.global [%0], [%1], 16;" :: "r"(dst), "l"(src) : "memory")
#define CP_COMMIT()  asm volatile("cp.async.commit_group;" ::: "memory")
#define CP_WAIT0()   asm volatile("cp.async.wait_group 0;" ::: "memory")
#define STS128(addr, v0, v1, v2, v3) \
    asm volatile("st.shared.v4.b32 [%0], {%1,%2,%3,%4};" \
        :: "r"(addr), "r"(v0), "r"(v1), "r"(v2), "r"(v3) : "memory")

__device__ __forceinline__ uint32_t splitpack(float v) {
    unsigned short h = __half_as_ushort(__float2half_rn(v));
    float r = v - __half2float(__ushort_as_half(h));
    unsigned short l = __half_as_ushort(__float2half_rn(r));
    return ((uint32_t)h << 16) | (uint32_t)l;
}

// ================= prep kernels =================
__global__ void zero_k() {
    const size_t n0 = (8*3*17161 + 17168) / 4;
    const size_t n1 = (8*256*4489) / 4;
    const size_t n2 = (8*256*1156) / 4;
    size_t i = (size_t)blockIdx.x * 256 + threadIdx.x;
    const uint4 z = {0, 0, 0, 0};
    if (i < n0) { ((uint4*)g_xs)[i] = z; return; }
    i -= n0;
    if (i < n1) { ((uint4*)g_h1s)[i] = z; return; }
    i -= n1;
    if (i < n2) { ((uint4*)g_acts)[i] = z; return; }
    i -= n2;
    if (i < n2) { ((uint4*)g_rs)[i] = z; return; }
    i -= n2;
    if (i < n2) { ((uint4*)g_d0s)[i] = z; return; }
}
__global__ void wtrans(const float* __restrict__ src, float* __restrict__ dst,
                       int Cout, int K) {
    int i = blockIdx.x * 256 + threadIdx.x;
    if (i >= Cout * K) return;
    int k = i / Cout, oc = i - k * Cout;
    dst[i] = src[(size_t)oc * K + k];
}
__global__ void xsplit(const float* __restrict__ x, float SA) {
    int i = blockIdx.x * 256 + threadIdx.x;
    if (i >= 8*3*16384) return;
    int pl = i >> 14, w = i & 16383;
    int y = w >> 7, xx = w & 127;
    g_xs[(size_t)pl * 17161 + (y + 1) * 131 + xx + 1] = splitpack(x[i] * SA);
}
__global__ void wsplit(const float* __restrict__ src, uint32_t* __restrict__ dst,
                       int Ksrc, int Kpad, float SW) {
    int u = blockIdx.x * 256 + threadIdx.x;
    if (u >= 256 * Kpad) return;
    int w = u & 3, c = (u >> 2) & 7, oc = (u >> 5) & 255, s = u >> 13;
    int kb = 32 * s + 8 * (c & 3) + 2 * w;
    float v0 = (kb     < Ksrc) ? src[(size_t)oc * Ksrc + kb]     * SW : 0.f;
    float v1 = (kb + 1 < Ksrc) ? src[(size_t)oc * Ksrc + kb + 1] * SW : 0.f;
    unsigned short h0 = __half_as_ushort(__float2half_rn(v0));
    unsigned short h1 = __half_as_ushort(__float2half_rn(v1));
    uint32_t val;
    if (c < 4) val = (uint32_t)h0 | ((uint32_t)h1 << 16);
    else {
        unsigned short l0 = __half_as_ushort(__float2half_rn(v0 - __half2float(__ushort_as_half(h0))));
        unsigned short l1 = __half_as_ushort(__float2half_rn(v1 - __half2float(__ushort_as_half(h1))));
        val = (uint32_t)l0 | ((uint32_t)l1 << 16);
    }
    dst[u] = val;
}
__global__ void wt1split(const float* __restrict__ w, uint32_t* __restrict__ dst, float SW) {
    int u = blockIdx.x * 256 + threadIdx.x;   // 4*256*1024
    int cls = u >> 18;
    int r = u & 262143;
    int ww = r & 3, c = (r >> 2) & 7, oc = (r >> 5) & 255, s = r >> 13;
    int ry = cls >> 1, rx = cls & 1;
    int kb = 32 * s + 8 * (c & 3) + 2 * ww;
    float v[2];
#pragma unroll
    for (int j = 0; j < 2; j++) {
        int k = kb + j;
        int ic = k >> 2, t = k & 3;
        int a = t >> 1, bb = t & 1;
        int ky = ry ? (a ? 2 : 0) : (a ? 3 : 1);
        int kx = rx ? (bb ? 2 : 0) : (bb ? 3 : 1);
        v[j] = w[((size_t)(ic * 256 + oc)) * 16 + ky * 4 + kx] * SW;
    }
    unsigned short h0 = __half_as_ushort(__float2half_rn(v[0]));
    unsigned short h1 = __half_as_ushort(__float2half_rn(v[1]));
    uint32_t val;
    if (c < 4) val = (uint32_t)h0 | ((uint32_t)h1 << 16);
    else {
        unsigned short l0 = __half_as_ushort(__float2half_rn(v[0] - __half2float(__ushort_as_half(h0))));
        unsigned short l1 = __half_as_ushort(__float2half_rn(v[1] - __half2float(__ushort_as_half(h1))));
        val = (uint32_t)l0 | ((uint32_t)l1 << 16);
    }
    dst[u] = val;
}
__global__ void cbnorm_k(const float* __restrict__ cb) {
    int k = blockIdx.x * 64 + threadIdx.x;
    if (k >= 512) return;
    const float* r = cb + (size_t)k * 64;
    float s0 = 0, s1 = 0, s2 = 0, s3 = 0;
#pragma unroll
    for (int c = 0; c < 64; c += 4) {
        s0 += r[c]*r[c]; s1 += r[c+1]*r[c+1]; s2 += r[c+2]*r[c+2]; s3 += r[c+3]*r[c+3];
    }
    g_cbn[k] = (s0 + s1) + (s2 + s3);
}

// ================= tensor-core conv (mma.sync fp16-split) =================
// Gather kinds G: 0=kc1(x 131-pad), 1=kc2(h1 67-pad), 2=3x3 s1 (34-pad),
//                 3=1x1 (34-pad), 4=t1 parity class (34-pad).
template<int G, int NT, int OUTF, int OUTS, int ADDRES, int ROUT,
         int OWB, int MIMG, int PS, int PW>
__global__ __launch_bounds__(256) void tconv(
    const uint32_t* __restrict__ inS, const uint32_t* __restrict__ wS,
    const float* __restrict__ bias, const float* __restrict__ res,
    float* __restrict__ outF, uint32_t* __restrict__ outS,
    int K, int Cout, float SINV, float SAN)
{
    extern __shared__ __align__(128) char smem[];
    const uint32_t sb0 = (smem_u32(smem) + 127) & ~127u;
    const int tid = threadIdx.x, lane = tid & 31, wid = tid >> 5;
    const int zi = blockIdx.z;
    int b, ry = 0, rx = 0, doy0 = 0, doy1 = 0, dox0 = 0, dox1 = 0;
    const uint32_t* wg = wS;
    if (G == 4) {
        b = zi >> 2; int cls = zi & 3;
        ry = cls >> 1; rx = cls & 1;
        doy0 = (ry ? 1 : 0) * 34; doy1 = (ry ? 0 : -1) * 34;
        dox0 = rx ? 1 : 0;        dox1 = rx ? 0 : -1;
        wg = wS + (size_t)cls * 262144;
    } else b = zi;
    const int m0 = blockIdx.x * 128;
    const int n0 = blockIdx.y * 128;
    const int CIS = (G == 0) ? 3*17161 : (G == 1) ? 256*4489 : 256*1156;
    const uint32_t* inb = inS + (size_t)b * CIS;

    // thread-work mapping: rows {rb, rb+64}, chunk group cg (4 k-pairs)
    const int rb = (lane & 7) | (wid << 3);
    const int cg = lane >> 3;
    int m2[2];
#pragma unroll
    for (int r2 = 0; r2 < 2; r2++) {
        int m = m0 + rb + r2 * 64;
        if      (G == 0) m2[r2] = 262 * (m >> 6) + 2 * (m & 63);
        else if (G == 1) m2[r2] = 134 * (m >> 5) + 2 * (m & 31);
        else if (G == 2) m2[r2] = 34 * (m >> 5) + (m & 31);
        else             m2[r2] = 34 * (m >> 5) + (m & 31) + 35;  // G3, G4
    }

    uint32_t stE[2][8];

    auto GA = [&](int s) {
        const int kb = (s << 5) + (cg << 3);
        int dlt[8];
#pragma unroll
        for (int u = 0; u < 8; u++) {
            int k = kb + u;
            if      (G == 0) dlt[u] = (k >> 4) * 17161 + ((k >> 2) & 3) * 131 + (k & 3);
            else if (G == 1) dlt[u] = (k >> 4) * 4489  + ((k >> 2) & 3) * 67  + (k & 3);
            else if (G == 2) { int ic = k / 9; int tap = k - ic * 9; int ky = tap / 3;
                               dlt[u] = ic * 1156 + ky * 34 + (tap - ky * 3); }
            else if (G == 3) dlt[u] = k * 1156;
            else { int ic = k >> 2; int a = (k >> 1) & 1; int b2 = k & 1;
                   dlt[u] = ic * 1156 + (a ? doy1 : doy0) + (b2 ? dox1 : dox0); }
        }
#pragma unroll
        for (int r2 = 0; r2 < 2; r2++)
#pragma unroll
            for (int u = 0; u < 8; u++)
                stE[r2][u] = inb[m2[r2] + dlt[u]];
    };
    auto STA = [&](int bufid) {
        const uint32_t Ab = sb0 + bufid * 32768;
#pragma unroll
        for (int r2 = 0; r2 < 2; r2++) {
            int r = rb + r2 * 64;
            uint32_t h0 = __byte_perm(stE[r2][0], stE[r2][1], 0x7632);
            uint32_t h1 = __byte_perm(stE[r2][2], stE[r2][3], 0x7632);
            uint32_t h2 = __byte_perm(stE[r2][4], stE[r2][5], 0x7632);
            uint32_t h3 = __byte_perm(stE[r2][6], stE[r2][7], 0x7632);
            uint32_t aH = Ab + (uint32_t)r * 128 + ((uint32_t)(cg ^ (r & 7)) << 4);
            STS128(aH, h0, h1, h2, h3);
            if (NT == 3) {
                uint32_t l0 = __byte_perm(stE[r2][0], stE[r2][1], 0x5410);
                uint32_t l1 = __byte_perm(stE[r2][2], stE[r2][3], 0x5410);
                uint32_t l2 = __byte_perm(stE[r2][4], stE[r2][5], 0x5410);
                uint32_t l3 = __byte_perm(stE[r2][6], stE[r2][7], 0x5410);
                uint32_t aL = Ab + (uint32_t)r * 128 + ((uint32_t)((cg + 4) ^ (r & 7)) << 4);
                STS128(aL, l0, l1, l2, l3);
            }
        }
    };
    auto GB = [&](int s, int bufid) {
        const uint32_t Bb = sb0 + bufid * 32768 + 16384;
#pragma unroll
        for (int i = 0; i < 4; i++) {
            int q = tid + i * 256;
            int r = q >> 3, cc = q & 7;
            const uint32_t* src = wg + (((size_t)s * 256 + n0 + r) * 8 + cc) * 4;
            uint32_t dst = Bb + (uint32_t)r * 128 + ((uint32_t)(cc ^ (r & 7)) << 4);
            CP_ASYNC16(dst, src);
        }
        CP_COMMIT();
    };

    const int wm = wid & 3, wn = wid >> 2;
    float acc[2][8][4] = {};
    const int rl = lane & 15, kc = lane >> 4;

    const int NS = K >> 5;
    GB(0, 0); GA(0); STA(0);
    CP_WAIT0();
    __syncthreads();
    for (int s = 0; s < NS; s++) {
        if (s + 1 < NS) { GB(s + 1, (s + 1) & 1); GA(s + 1); }
        const uint32_t Ab = sb0 + (s & 1) * 32768, Bb = Ab + 16384;
#pragma unroll
        for (int g = 0; g < 2; g++) {
            uint32_t aH[2][4], aL[2][4];
#pragma unroll
            for (int mt = 0; mt < 2; mt++) {
                int r = wm * 32 + mt * 16 + rl;
                uint32_t base = Ab + (uint32_t)r * 128;
                int cH = 2 * g + kc;
                LDSM_X4(aH[mt], base + (uint32_t)((cH ^ (r & 7)) << 4));
                if (NT == 3)
                    LDSM_X4(aL[mt], base + (uint32_t)(((cH + 4) ^ (r & 7)) << 4));
            }
            uint32_t bH[8][2], bL[8][2];
#pragma unroll
            for (int t = 0; t < 4; t++) {
                int r = wn * 64 + t * 16 + rl;
                uint32_t base = Bb + (uint32_t)r * 128;
                int cH = 2 * g + kc;
                uint32_t q[4];
                LDSM_X4(q, base + (uint32_t)((cH ^ (r & 7)) << 4));
                bH[2*t][0] = q[0]; bH[2*t+1][0] = q[1]; bH[2*t][1] = q[2]; bH[2*t+1][1] = q[3];
                LDSM_X4(q, base + (uint32_t)(((cH + 4) ^ (r & 7)) << 4));
                bL[2*t][0] = q[0]; bL[2*t+1][0] = q[1]; bL[2*t][1] = q[2]; bL[2*t+1][1] = q[3];
            }
#pragma unroll
            for (int mt = 0; mt < 2; mt++)
#pragma unroll
                for (int nt = 0; nt < 8; nt++) {
                    MMA_F16(acc[mt][nt], aH[mt], bH[nt]);
                    MMA_F16(acc[mt][nt], aH[mt], bL[nt]);
                    if (NT == 3) MMA_F16(acc[mt][nt], aL[mt], bH[nt]);
                }
        }
        if (s + 1 < NS) STA((s + 1) & 1);
        CP_WAIT0();
        __syncthreads();
    }

    // ---- epilogue
#pragma unroll
    for (int mt = 0; mt < 2; mt++) {
        int mb = m0 + wm * 32 + mt * 16 + (lane >> 2);
#pragma unroll
        for (int nt = 0; nt < 8; nt++) {
            int ocb = n0 + wn * 64 + nt * 8 + ((lane & 3) << 1);
#pragma unroll
            for (int h = 0; h < 2; h++) {
                int m = mb + h * 8;
#pragma unroll
                for (int q = 0; q < 2; q++) {
                    int oc = ocb + q;
                    float v = acc[mt][nt][h * 2 + q] * SINV + __ldg(bias + oc);
                    size_t ob;
                    if (G == 4) {
                        int y = m >> 5, x = m & 31;
                        ob = ((size_t)(b * Cout + oc)) * 4096 + (size_t)(2*y + ry) * 64 + (2*x + rx);
                    } else {
                        ob = ((size_t)b * Cout + oc) * MIMG + m;
                    }
                    if (ADDRES) v += res[ob];
                    if (ROUT) v = fmaxf(v, 0.f);
                    if (OUTF) outF[ob] = v;
                    if (OUTS) {
                        int y = m >> OWB, x = m & ((1 << OWB) - 1);
                        size_t obS = ((size_t)(b * Cout + oc)) * PS + (size_t)(y + 1) * PW + x + 1;
                        outS[obS] = splitpack(fmaxf(v, 0.f) * SAN);
                    }
                }
            }
        }
    }
}

// ================= fp32 1x1 conv (toz / fz) =================
#define FMA16S \
    acc[0][0] += bv.x*a.x; acc[0][1] += bv.x*a.y; acc[0][2] += bv.x*a.z; acc[0][3] += bv.x*a.w; \
    acc[1][0] += bv.y*a.x; acc[1][1] += bv.y*a.y; acc[1][2] += bv.y*a.z; acc[1][3] += bv.y*a.w; \
    acc[2][0] += bv.z*a.x; acc[2][1] += bv.z*a.y; acc[2][2] += bv.z*a.z; acc[2][3] += bv.z*a.w; \
    acc[3][0] += bv.w*a.x; acc[3][1] += bv.w*a.y; acc[3][2] += bv.w*a.z; acc[3][3] += bv.w*a.w;

template<int ROUT, int OUTS>
__global__ __launch_bounds__(256) void conv1x1_k(
    const float* __restrict__ in, const float* __restrict__ wT,
    const float* __restrict__ bias,
    float* __restrict__ out, uint32_t* __restrict__ outS,
    int Cin, int Cout, float SAN)
{
    const int K = Cin;
    const int b  = blockIdx.z;
    const int m0 = blockIdx.x * 64;
    const int n0 = blockIdx.y * 64;
    __shared__ float As[16][64];
    __shared__ float Bs[16][64];
    const int tid = threadIdx.x;
    const int lm = tid & 63, lk = tid >> 6;
    const int mi = (tid & 15) << 2, ni = (tid >> 4) << 2;
    const float* inb = in + (size_t)b * Cin * 1024;

    float acc[4][4] = {};
    for (int k0 = 0; k0 < K; k0 += 16) {
#pragma unroll
        for (int i = 0; i < 4; i++) {
            int k = k0 + lk + i * 4;
            As[lk + i * 4][lm] = inb[(size_t)k * 1024 + m0 + lm];
            Bs[lk + i * 4][lm] = wT[(size_t)k * Cout + n0 + lm];
        }
        __syncthreads();
#pragma unroll
        for (int kk = 0; kk < 16; kk++) {
            float4 a  = *(const float4*)&As[kk][mi];
            float4 bv = *(const float4*)&Bs[kk][ni];
            FMA16S
        }
        __syncthreads();
    }
    const int m = m0 + mi;
#pragma unroll
    for (int i = 0; i < 4; i++) {
        int oc = n0 + ni + i;
        size_t ob = ((size_t)b * Cout + oc) * 1024 + m;
        float bb = bias[oc];
        float4 r;
        r.x = acc[i][0] + bb; r.y = acc[i][1] + bb;
        r.z = acc[i][2] + bb; r.w = acc[i][3] + bb;
        if (ROUT) {
            r.x = fmaxf(r.x, 0.f); r.y = fmaxf(r.y, 0.f);
            r.z = fmaxf(r.z, 0.f); r.w = fmaxf(r.w, 0.f);
        }
        if (OUTS) {
            int y = m >> 5, x = m & 31;
            size_t base = ((size_t)b * Cout + oc) * 1156 + (size_t)(y + 1) * 34 + x + 1;
            outS[base + 0] = splitpack(fmaxf(r.x, 0.f) * SAN);
            outS[base + 1] = splitpack(fmaxf(r.y, 0.f) * SAN);
            outS[base + 2] = splitpack(fmaxf(r.z, 0.f) * SAN);
            outS[base + 3] = splitpack(fmaxf(r.w, 0.f) * SAN);
        } else {
            *(float4*)&out[ob] = r;
        }
    }
}

// ================= t2 (256 -> 3, 64x64 -> 128x128) + sigmoid =================
__global__ __launch_bounds__(128) void t2_k(const float* __restrict__ w,
                                            const float* __restrict__ bias,
                                            float* __restrict__ out)
{
    const int cls = blockIdx.z, b = blockIdx.y;
    const int ry = cls >> 1, rx = cls & 1;
    const int oy0 = ry ? 1 : 0, oy1 = ry ? 0 : -1;
    const int ox1 = rx ? 0 : -1;
    __shared__ float ws[3072];
    for (int i = threadIdx.x; i < 3072; i += 128) {
        int ic = i / 12, r = i - ic * 12;
        int t = r / 3, oc = r - t * 3;
        int a = t >> 1, bb = t & 1;
        int ky = ry ? (a ? 2 : 0) : (a ? 3 : 1);
        int kx = rx ? (bb ? 2 : 0) : (bb ? 3 : 1);
        ws[i] = w[((size_t)(ic * 3 + oc)) * 16 + ky * 4 + kx];
    }
    __syncthreads();
    const int t = blockIdx.x * 128 + threadIdx.x;
    const int yy = t >> 4;
    const int xg = (t & 15) << 2;
    const int basex = xg + ox1;
    const float* inb = g_d1 + (size_t)b * 256 * 4096;
    float acc[4][3] = {};
    for (int ic = 0; ic < 256; ic++) {
        const float* ip = inb + ic * 4096;
        float v[2][5];
#pragma unroll
        for (int a = 0; a < 2; a++) {
            int iy = yy + (a ? oy1 : oy0);
            bool okr = (unsigned)iy < 64u;
#pragma unroll
            for (int q = 0; q < 5; q++) {
                int ix = basex + q;
                v[a][q] = (okr && (unsigned)ix < 64u) ? ip[iy * 64 + ix] : 0.f;
            }
        }
        const float* wr = &ws[ic * 12];
#pragma unroll
        for (int p = 0; p < 4; p++)
#pragma unroll
            for (int bb2 = 0; bb2 < 2; bb2++) {
#pragma unroll
                for (int a = 0; a < 2; a++) {
                    float val = v[a][p + (bb2 ? 0 : 1)];
                    int ti = a * 2 + bb2;
                    acc[p][0] += val * wr[ti * 3 + 0];
                    acc[p][1] += val * wr[ti * 3 + 1];
                    acc[p][2] += val * wr[ti * 3 + 2];
                }
            }
    }
#pragma unroll
    for (int p = 0; p < 4; p++) {
        int oy = 2 * yy + ry, ox = 2 * (xg + p) + rx;
#pragma unroll
        for (int oc = 0; oc < 3; oc++) {
            float vv = acc[p][oc] + bias[oc];
            out[((size_t)(b * 3 + oc) * 128 + oy) * 128 + ox] = 1.f / (1.f + __expf(-vv));
        }
    }
}

// ================= VQ (chunked argmin) =================
__global__ __launch_bounds__(256) void vq_part(const float* __restrict__ cb)
{
    const int n = blockIdx.x * 256 + threadIdx.x;
    const int chunk = blockIdx.y;
    const int c0base = chunk * 128;
    const int b = n >> 10, s = n & 1023;
    const float* zp = g_ze + (size_t)b * 64 * 1024 + s;
    float z[64];
#pragma unroll
    for (int c = 0; c < 64; c++) z[c] = zp[(size_t)c * 1024];
    float z0 = 0, z1 = 0, z2a = 0, z3 = 0;
#pragma unroll
    for (int c = 0; c < 64; c += 4) {
        z0 += z[c]*z[c]; z1 += z[c+1]*z[c+1]; z2a += z[c+2]*z[c+2]; z3 += z[c+3]*z[c+3];
    }
    const float zn = (z0 + z1) + (z2a + z3);
    __shared__ float cbs[8192];
    for (int i = threadIdx.x; i < 8192; i += 256)
        cbs[i] = cb[(size_t)c0base * 64 + i];
    __syncthreads();
    float best = 3.4e38f; int bid = 0;
    for (int k = 0; k < 128; k++) {
        const float* cr = &cbs[k * 64];
        float d0 = 0, d1 = 0, d2 = 0, d3 = 0;
#pragma unroll
        for (int c = 0; c < 64; c += 4) {
            d0 += z[c]*cr[c]; d1 += z[c+1]*cr[c+1]; d2 += z[c+2]*cr[c+2]; d3 += z[c+3]*cr[c+3];
        }
        float dot = (d0 + d1) + (d2 + d3);
        float score = (zn - 2.0f * dot) + g_cbn[c0base + k];
        if (score < best) { best = score; bid = c0base + k; }
    }
    g_vqs[chunk * 8192 + n] = best;
    g_vqi[chunk * 8192 + n] = bid;
}
__global__ __launch_bounds__(256) void vq_reduce(const float* __restrict__ cb)
{
    const int n = blockIdx.x * 256 + threadIdx.x;
    float best = g_vqs[n]; int bid = g_vqi[n];
#pragma unroll
    for (int ch = 1; ch < 4; ch++) {
        float s = g_vqs[ch * 8192 + n];
        int   i = g_vqi[ch * 8192 + n];
        if (s < best) { best = s; bid = i; }
    }
    g_ids[n] = bid;
    const int b = n >> 10, s2 = n & 1023;
    const float* code = cb + (size_t)bid * 64;
    float* ep = g_ek + (size_t)b * 64 * 1024 + s2;
#pragma unroll
    for (int c = 0; c < 64; c++) ep[(size_t)c * 1024] = code[c];
}

// ================= pack tuple tail =================
__global__ void pack_k(float* __restrict__ out, int out_size)
{
    int i = blockIdx.x * 256 + threadIdx.x;
    if (i < 524288) {
        int o = 393216 + i;
        if (o < out_size) out[o] = g_ze[i];
    } else if (i < 1048576) {
        int j = i - 524288;
        int o = 917504 + j;
        if (o < out_size) out[o] = g_ek[j];
    } else if (i < 1056768) {
        int j = i - 1048576;
        int o = 1441792 + j;
        if (o < out_size) out[o] = (float)g_ids[j];
    }
}

// ================= launch =================
static constexpr int SMEM_TC = 65536 + 256;

extern "C" void kernel_launch(void* const* d_in, const int* in_sizes, int n_in,
                              void* d_out, int out_size)
{
    const float* x     = (const float*)d_in[0];
    const float* c1_w  = (const float*)d_in[1];
    const float* c1_b  = (const float*)d_in[2];
    const float* c2_w  = (const float*)d_in[3];
    const float* c2_b  = (const float*)d_in[4];
    const float* r0_w3 = (const float*)d_in[5];
    const float* r0_b3 = (const float*)d_in[6];
    const float* r0_w1 = (const float*)d_in[7];
    const float* r0_b1 = (const float*)d_in[8];
    const float* r1_w3 = (const float*)d_in[9];
    const float* r1_b3 = (const float*)d_in[10];
    const float* r1_w1 = (const float*)d_in[11];
    const float* r1_b1 = (const float*)d_in[12];
    const float* toz_w = (const float*)d_in[13];
    const float* toz_b = (const float*)d_in[14];
    const float* cb    = (const float*)d_in[15];
    const float* fz_w  = (const float*)d_in[16];
    const float* fz_b  = (const float*)d_in[17];
    const float* t1_w  = (const float*)d_in[18];
    const float* t1_b  = (const float*)d_in[19];
    const float* t2_w  = (const float*)d_in[20];
    const float* t2_b  = (const float*)d_in[21];
    float* out = (float*)d_out;

    void* p;
#define GETF(var, sym) cudaGetSymbolAddress(&p, sym); float* var = (float*)p;
#define GETU(var, sym) cudaGetSymbolAddress(&p, sym); uint32_t* var = (uint32_t*)p;
    GETF(h2p,  g_h2)   GETF(zep,  g_ze)   GETF(ekp,  g_ek)   GETF(d1p,  g_d1)
    GETF(wtoz, g_wtoz) GETF(wfz,  g_wfz)
    GETU(xs,   g_xs)   GETU(h1s,  g_h1s)  GETU(acts, g_acts) GETU(rs,   g_rs)
    GETU(d0s,  g_d0s)
    GETU(wc1s, g_wc1s) GETU(wc2s, g_wc2s) GETU(wr03s,g_wr03s) GETU(wr01s,g_wr01s)
    GETU(wr13s,g_wr13s) GETU(wr11s,g_wr11s) GETU(wt1s, g_wt1s)
#undef GETF
#undef GETU

    // tconv instantiations  <G,NT,OUTF,OUTS,ADDRES,ROUT,OWB,MIMG,PS,PW>
    auto* kc1  = tconv<0, 3, 0, 1, 0, 1, 6, 4096, 4489, 67>;
    auto* kc2  = tconv<1, 3, 1, 1, 0, 1, 5, 1024, 1156, 34>;
    auto* kr3  = tconv<2, 3, 0, 1, 0, 0, 5, 1024, 1156, 34>;
    auto* kr1a = tconv<3, 3, 1, 1, 1, 0, 5, 1024, 1156, 34>;
    auto* kr1b = tconv<3, 3, 1, 0, 1, 0, 5, 1024, 1156, 34>;
    auto* kt1  = tconv<4, 2, 1, 0, 0, 1, 5, 1024, 1156, 34>;
    cudaFuncSetAttribute(kc1,  cudaFuncAttributeMaxDynamicSharedMemorySize, SMEM_TC);
    cudaFuncSetAttribute(kc2,  cudaFuncAttributeMaxDynamicSharedMemorySize, SMEM_TC);
    cudaFuncSetAttribute(kr3,  cudaFuncAttributeMaxDynamicSharedMemorySize, SMEM_TC);
    cudaFuncSetAttribute(kr1a, cudaFuncAttributeMaxDynamicSharedMemorySize, SMEM_TC);
    cudaFuncSetAttribute(kr1b, cudaFuncAttributeMaxDynamicSharedMemorySize, SMEM_TC);
    cudaFuncSetAttribute(kt1,  cudaFuncAttributeMaxDynamicSharedMemorySize, SMEM_TC);

    const float SA = 256.f, SW = 1024.f;
    const float SI  = 1.f / (256.f * 1024.f);
    const float SAT = 16384.f, SIT = 1.f / (16384.f * 1024.f);

    const int ZTOT = ((8*3*17161 + 17168) + 8*256*4489 + 3 * (8*256*1156)) / 4;

    // launch order: kernel index 3 (0-based) == kc1, the profiled slot
    zero_k<<<(ZTOT + 255) / 256, 256>>>();                               // 0
    xsplit<<<(8*3*16384) / 256, 256>>>(x, SA);                           // 1
    wsplit<<<(256*64)   / 256, 256>>>(c1_w, wc1s, 48, 64, SW);           // 2
    kc1<<<dim3(32,2,8), 256, SMEM_TC>>>(xs, wc1s, c1_b, nullptr,         // 3 <- profiled
        nullptr, h1s, 64, 256, SI, SA);
    wsplit<<<(256*4096) / 256, 256>>>(c2_w, wc2s, 4096, 4096, SW);       // 4
    kc2<<<dim3(8,2,8), 256, SMEM_TC>>>(h1s, wc2s, c2_b, nullptr,         // 5
        h2p, acts, 4096, 256, SI, SA);

    wsplit<<<(256*2304) / 256, 256>>>(r0_w3, wr03s, 2304, 2304, SW);
    kr3 <<<dim3(8,2,8), 256, SMEM_TC>>>(acts, wr03s, r0_b3, nullptr, nullptr, rs, 2304, 256, SI, SA);
    wsplit<<<(256*256)  / 256, 256>>>(r0_w1, wr01s, 256, 256, SW);
    kr1a<<<dim3(8,2,8), 256, SMEM_TC>>>(rs,   wr01s, r0_b1, h2p,     h2p, acts, 256,  256, SI, SA);
    wsplit<<<(256*2304) / 256, 256>>>(r1_w3, wr13s, 2304, 2304, SW);
    kr3 <<<dim3(8,2,8), 256, SMEM_TC>>>(acts, wr13s, r1_b3, nullptr, nullptr, rs, 2304, 256, SI, SA);
    wsplit<<<(256*256)  / 256, 256>>>(r1_w1, wr11s, 256, 256, SW);
    kr1b<<<dim3(8,2,8), 256, SMEM_TC>>>(rs,   wr11s, r1_b1, h2p,     h2p, nullptr, 256, 256, SI, 0.f);

    wtrans<<<(256*64) / 256, 256>>>(toz_w, wtoz, 64, 256);
    conv1x1_k<0,0><<<dim3(16,1,8), 256>>>(h2p, wtoz, toz_b, zep, nullptr, 256, 64, 0.f);

    // vector quantization
    cbnorm_k<<<8, 64>>>(cb);
    vq_part<<<dim3(32,4), 256>>>(cb);
    vq_reduce<<<32, 256>>>(cb);

    // decoder
    wtrans<<<(64*256) / 256, 256>>>(fz_w, wfz, 256, 64);
    conv1x1_k<1,1><<<dim3(16,4,8), 256>>>(ekp, wfz, fz_b, nullptr, d0s, 64, 256, SAT);
    wt1split<<<(4*256*1024) / 256, 256>>>(t1_w, wt1s, SW);
    kt1<<<dim3(8,2,32), 256, SMEM_TC>>>(d0s, wt1s, t1_b, nullptr, d1p, nullptr, 1024, 256, SIT, 0.f);
    t2_k<<<dim3(8,8,4), 128>>>(t2_w, t2_b, out);

    // pack z_e / e_k / ids
    pack_k<<<4128, 256>>>(out, out_size);
}

// round 11
// speedup vs baseline: 2.6691x; 1.0097x over previous
#include <cuda_runtime.h>
#include <cuda_fp16.h>
#include <cstdint>
#include <math.h>

// ================= static shapes =================
// B=8, HID=256, ZC=64, K=512
__device__ float    g_h2[8*256*32*32];
__device__ float    g_ze[8*64*32*32];
__device__ float    g_ek[8*64*32*32];
__device__ float    g_d1[8*256*64*64];
__device__ int      g_ids[8192];
__device__ float    g_cbn[512];
__device__ float    g_wtoz[256*64];
__device__ float    g_wfz [64*256];
__device__ float    g_vqs[4*8192];
__device__ int      g_vqi[4*8192];
// padded split activations (u32 = hi16<<16 | lo16), pre-scaled, post-relu, zero halos
__device__ uint32_t g_xs  [8*3*17161 + 17168];
__device__ uint32_t g_h1s [8*256*4489];
__device__ uint32_t g_acts[8*256*1156];
__device__ uint32_t g_rs  [8*256*1156];
__device__ uint32_t g_d0s [8*256*1156];
// split weights, per-stage chunk layout
__device__ uint32_t g_wc1s [256*64];
__device__ uint32_t g_wc2s [256*4096];
__device__ uint32_t g_wr03s[256*2304];
__device__ uint32_t g_wr01s[256*256];
__device__ uint32_t g_wr13s[256*2304];
__device__ uint32_t g_wr11s[256*256];
__device__ uint32_t g_wt1s [4*256*1024];

// ================= helpers =================
__device__ __forceinline__ uint32_t smem_u32(const void* p) {
    uint32_t a;
    asm("{ .reg .u64 t; cvta.to.shared.u64 t, %1; cvt.u32.u64 %0, t; }" : "=r"(a) : "l"(p));
    return a;
}
#define LDSM_X4(r, addr) \
    asm volatile("ldmatrix.sync.aligned.m8n8.x4.shared.b16 {%0,%1,%2,%3}, [%4];" \
        : "=r"((r)[0]), "=r"((r)[1]), "=r"((r)[2]), "=r"((r)[3]) : "r"(addr))
#define MMA_F16(d, a, b) \
    asm volatile("mma.sync.aligned.m16n8k16.row.col.f32.f16.f16.f32 " \
        "{%0,%1,%2,%3}, {%4,%5,%6,%7}, {%8,%9}, {%0,%1,%2,%3};" \
        : "+f"((d)[0]), "+f"((d)[1]), "+f"((d)[2]), "+f"((d)[3]) \
        : "r"((a)[0]), "r"((a)[1]), "r"((a)[2]), "r"((a)[3]), "r"((b)[0]), "r"((b)[1]))
#define CP_ASYNC16(dst, src) \
    asm volatile("cp.async.cg.shared.global [%0], [%1], 16;" :: "r"(dst), "l"(src) : "memory")
#define CP_COMMIT()  asm volatile("cp.async.commit_group;" ::: "memory")
#define CP_WAIT0()   asm volatile("cp.async.wait_group 0;" ::: "memory")
#define STS128(addr, v0, v1, v2, v3) \
    asm volatile("st.shared.v4.b32 [%0], {%1,%2,%3,%4};" \
        :: "r"(addr), "r"(v0), "r"(v1), "r"(v2), "r"(v3) : "memory")

__device__ __forceinline__ uint32_t splitpack(float v) {
    unsigned short h = __half_as_ushort(__float2half_rn(v));
    float r = v - __half2float(__ushort_as_half(h));
    unsigned short l = __half_as_ushort(__float2half_rn(r));
    return ((uint32_t)h << 16) | (uint32_t)l;
}
__device__ __forceinline__ uint32_t wsplit_val(const float* src, int Ksrc, float SW, int u) {
    int w = u & 3, c = (u >> 2) & 7, oc = (u >> 5) & 255, s = u >> 13;
    int kb = 32 * s + 8 * (c & 3) + 2 * w;
    float v0 = (kb     < Ksrc) ? src[(size_t)oc * Ksrc + kb]     * SW : 0.f;
    float v1 = (kb + 1 < Ksrc) ? src[(size_t)oc * Ksrc + kb + 1] * SW : 0.f;
    unsigned short h0 = __half_as_ushort(__float2half_rn(v0));
    unsigned short h1 = __half_as_ushort(__float2half_rn(v1));
    if (c < 4) return (uint32_t)h0 | ((uint32_t)h1 << 16);
    unsigned short l0 = __half_as_ushort(__float2half_rn(v0 - __half2float(__ushort_as_half(h0))));
    unsigned short l1 = __half_as_ushort(__float2half_rn(v1 - __half2float(__ushort_as_half(h1))));
    return (uint32_t)l0 | ((uint32_t)l1 << 16);
}

// ================= prep kernels =================
// zero only halos (interiors are rewritten by producers each launch) + kc1 guard
__global__ void halo_zero() {
    int i = blockIdx.x * 256 + threadIdx.x;
    // xs: 24 planes x 777 halo cells
    if (i < 24 * 777) {
        int pl = i / 777, j = i - pl * 777;
        int y, x;
        if (j < 393) { int r = j / 131; y = (r == 0) ? 0 : (r == 1 ? 129 : 130); x = j % 131; }
        else { int j2 = j - 393; y = 1 + j2 / 3; int c = j2 % 3; x = (c == 0) ? 0 : (c == 1 ? 129 : 130); }
        g_xs[(size_t)pl * 17161 + y * 131 + x] = 0;
        return;
    }
    i -= 24 * 777;
    if (i < 17168) { g_xs[8*3*17161 + i] = 0; return; }   // guard plane (kc1 K-pad reads)
    i -= 17168;
    // h1s: 2048 planes x 393 halo cells (67x67, interior 64x64 @ (1,1))
    if (i < 2048 * 393) {
        int pl = i / 393, j = i - pl * 393;
        int y, x;
        if (j < 201) { int r = j / 67; y = (r == 0) ? 0 : (r == 1 ? 65 : 66); x = j % 67; }
        else { int j2 = j - 201; y = 1 + j2 / 3; int c = j2 % 3; x = (c == 0) ? 0 : (c == 1 ? 65 : 66); }
        g_h1s[(size_t)pl * 4489 + y * 67 + x] = 0;
        return;
    }
    i -= 2048 * 393;
    // acts/rs/d0s: 3 x 2048 planes x 132 halo cells (34x34, interior 32x32 @ (1,1))
    if (i < 3 * 2048 * 132) {
        int arr = i / (2048 * 132);
        int r2 = i - arr * 2048 * 132;
        int pl = r2 / 132, j = r2 - pl * 132;
        int y, x;
        if (j < 68) { y = (j < 34) ? 0 : 33; x = j % 34; }
        else { int j2 = j - 68; y = 1 + (j2 >> 1); x = (j2 & 1) ? 33 : 0; }
        uint32_t* base = (arr == 0) ? g_acts : (arr == 1) ? g_rs : g_d0s;
        base[(size_t)pl * 1156 + y * 34 + x] = 0;
    }
}
// fused encoder prep: xsplit + c1 weight split + c2 weight split
__global__ void prep_enc(const float* __restrict__ x, const float* __restrict__ c1_w,
                         const float* __restrict__ c2_w, float SA, float SW) {
    int i = blockIdx.x * 256 + threadIdx.x;
    if (i < 8*3*16384) {
        int pl = i >> 14, w = i & 16383;
        int y = w >> 7, xx = w & 127;
        g_xs[(size_t)pl * 17161 + (y + 1) * 131 + xx + 1] = splitpack(x[i] * SA);
        return;
    }
    i -= 8*3*16384;
    if (i < 256*64) { g_wc1s[i] = wsplit_val(c1_w, 48, SW, i); return; }
    i -= 256*64;
    if (i < 256*4096) g_wc2s[i] = wsplit_val(c2_w, 4096, SW, i);
}
__global__ void wsplit(const float* __restrict__ src, uint32_t* __restrict__ dst,
                       int Ksrc, int Kpad, float SW) {
    int u = blockIdx.x * 256 + threadIdx.x;
    if (u >= 256 * Kpad) return;
    dst[u] = wsplit_val(src, Ksrc, SW, u);
}
__global__ void wt1split(const float* __restrict__ w, uint32_t* __restrict__ dst, float SW) {
    int u = blockIdx.x * 256 + threadIdx.x;
    int cls = u >> 18;
    int r = u & 262143;
    int ww = r & 3, c = (r >> 2) & 7, oc = (r >> 5) & 255, s = r >> 13;
    int ry = cls >> 1, rx = cls & 1;
    int kb = 32 * s + 8 * (c & 3) + 2 * ww;
    float v[2];
#pragma unroll
    for (int j = 0; j < 2; j++) {
        int k = kb + j;
        int ic = k >> 2, t = k & 3;
        int a = t >> 1, bb = t & 1;
        int ky = ry ? (a ? 2 : 0) : (a ? 3 : 1);
        int kx = rx ? (bb ? 2 : 0) : (bb ? 3 : 1);
        v[j] = w[((size_t)(ic * 256 + oc)) * 16 + ky * 4 + kx] * SW;
    }
    unsigned short h0 = __half_as_ushort(__float2half_rn(v[0]));
    unsigned short h1 = __half_as_ushort(__float2half_rn(v[1]));
    uint32_t val;
    if (c < 4) val = (uint32_t)h0 | ((uint32_t)h1 << 16);
    else {
        unsigned short l0 = __half_as_ushort(__float2half_rn(v[0] - __half2float(__ushort_as_half(h0))));
        unsigned short l1 = __half_as_ushort(__float2half_rn(v[1] - __half2float(__ushort_as_half(h1))));
        val = (uint32_t)l0 | ((uint32_t)l1 << 16);
    }
    dst[u] = val;
}
__global__ void wtrans(const float* __restrict__ src, float* __restrict__ dst,
                       int Cout, int K) {
    int i = blockIdx.x * 256 + threadIdx.x;
    if (i >= Cout * K) return;
    int k = i / Cout, oc = i - k * Cout;
    dst[i] = src[(size_t)oc * K + k];
}
__global__ void cbnorm_k(const float* __restrict__ cb) {
    int k = blockIdx.x * 64 + threadIdx.x;
    if (k >= 512) return;
    const float* r = cb + (size_t)k * 64;
    float s0 = 0, s1 = 0, s2 = 0, s3 = 0;
#pragma unroll
    for (int c = 0; c < 64; c += 4) {
        s0 += r[c]*r[c]; s1 += r[c+1]*r[c+1]; s2 += r[c+2]*r[c+2]; s3 += r[c+3]*r[c+3];
    }
    g_cbn[k] = (s0 + s1) + (s2 + s3);
}

// ================= tensor-core conv (mma.sync fp16-split) =================
// CTA tile 64(M) x 128(N), BK=32; 8 warps, each 32x32.
// G: 0=kc1(131-pad), 1=kc2(67-pad), 2=3x3 s1 (34-pad), 3=1x1 (34-pad), 4=t1 class.
template<int G, int NT, int OUTF, int OUTS, int ADDRES, int ROUT,
         int OWB, int MIMG, int PS, int PW>
__global__ __launch_bounds__(256) void tconv(
    const uint32_t* __restrict__ inS, const uint32_t* __restrict__ wS,
    const float* __restrict__ bias, const float* __restrict__ res,
    float* __restrict__ outF, uint32_t* __restrict__ outS,
    int K, int Cout, float SINV, float SAN)
{
    extern __shared__ __align__(128) char smem[];
    const uint32_t sb0 = (smem_u32(smem) + 127) & ~127u;
    const int tid = threadIdx.x, lane = tid & 31, wid = tid >> 5;
    const int zi = blockIdx.z;
    int b, ry = 0, rx = 0, doy0 = 0, doy1 = 0, dox0 = 0, dox1 = 0;
    const uint32_t* wg = wS;
    if (G == 4) {
        b = zi >> 2; int cls = zi & 3;
        ry = cls >> 1; rx = cls & 1;
        doy0 = (ry ? 1 : 0) * 34; doy1 = (ry ? 0 : -1) * 34;
        dox0 = rx ? 1 : 0;        dox1 = rx ? 0 : -1;
        wg = wS + (size_t)cls * 262144;
    } else b = zi;
    const int m0 = blockIdx.x * 64;
    const int n0 = blockIdx.y * 128;
    const int CIS = (G == 0) ? 3*17161 : (G == 1) ? 256*4489 : 256*1156;
    const uint32_t* inb = inS + (size_t)b * CIS;

    // one row + one chunk-group per thread
    const int rb = (lane & 7) | (wid << 3);     // 0..63
    const int cg = lane >> 3;                    // 0..3
    int m2;
    {
        int m = m0 + rb;
        if      (G == 0) m2 = 262 * (m >> 6) + 2 * (m & 63);
        else if (G == 1) m2 = 134 * (m >> 5) + 2 * (m & 31);
        else if (G == 2) m2 = 34 * (m >> 5) + (m & 31);
        else             m2 = 34 * (m >> 5) + (m & 31) + 35;
    }

    uint32_t stE[8];

    auto GA = [&](int s) {
        const int kb = (s << 5) + (cg << 3);
        int dlt[8];
#pragma unroll
        for (int u = 0; u < 8; u++) {
            int k = kb + u;
            if      (G == 0) dlt[u] = (k >> 4) * 17161 + ((k >> 2) & 3) * 131 + (k & 3);
            else if (G == 1) dlt[u] = (k >> 4) * 4489  + ((k >> 2) & 3) * 67  + (k & 3);
            else if (G == 2) { int ic = k / 9; int tap = k - ic * 9; int ky = tap / 3;
                               dlt[u] = ic * 1156 + ky * 34 + (tap - ky * 3); }
            else if (G == 3) dlt[u] = k * 1156;
            else { int ic = k >> 2; int a = (k >> 1) & 1; int b2 = k & 1;
                   dlt[u] = ic * 1156 + (a ? doy1 : doy0) + (b2 ? dox1 : dox0); }
        }
#pragma unroll
        for (int u = 0; u < 8; u++)
            stE[u] = inb[m2 + dlt[u]];
    };
    auto STA = [&](int bufid) {
        const uint32_t Ab = sb0 + bufid * 24576;
        const int r = rb;
        uint32_t h0 = __byte_perm(stE[0], stE[1], 0x7632);
        uint32_t h1 = __byte_perm(stE[2], stE[3], 0x7632);
        uint32_t h2 = __byte_perm(stE[4], stE[5], 0x7632);
        uint32_t h3 = __byte_perm(stE[6], stE[7], 0x7632);
        uint32_t aH = Ab + (uint32_t)r * 128 + ((uint32_t)(cg ^ (r & 7)) << 4);
        STS128(aH, h0, h1, h2, h3);
        if (NT == 3) {
            uint32_t l0 = __byte_perm(stE[0], stE[1], 0x5410);
            uint32_t l1 = __byte_perm(stE[2], stE[3], 0x5410);
            uint32_t l2 = __byte_perm(stE[4], stE[5], 0x5410);
            uint32_t l3 = __byte_perm(stE[6], stE[7], 0x5410);
            uint32_t aL = Ab + (uint32_t)r * 128 + ((uint32_t)((cg + 4) ^ (r & 7)) << 4);
            STS128(aL, l0, l1, l2, l3);
        }
    };
    auto GB = [&](int s, int bufid) {
        const uint32_t Bb = sb0 + bufid * 24576 + 8192;
#pragma unroll
        for (int i = 0; i < 4; i++) {
            int q = tid + i * 256;
            int r = q >> 3, cc = q & 7;
            const uint32_t* src = wg + (((size_t)s * 256 + n0 + r) * 8 + cc) * 4;
            uint32_t dst = Bb + (uint32_t)r * 128 + ((uint32_t)(cc ^ (r & 7)) << 4);
            CP_ASYNC16(dst, src);
        }
        CP_COMMIT();
    };

    const int wm = wid & 1, wn = wid >> 1;
    float acc[2][4][4] = {};
    const int rl = lane & 15, kc = lane >> 4;

    const int NS = K >> 5;
    GB(0, 0); GA(0); STA(0);
    CP_WAIT0();
    __syncthreads();
    for (int s = 0; s < NS; s++) {
        if (s + 1 < NS) { GB(s + 1, (s + 1) & 1); GA(s + 1); }
        const uint32_t Ab = sb0 + (s & 1) * 24576, Bb = Ab + 8192;
#pragma unroll
        for (int g = 0; g < 2; g++) {
            uint32_t aH[2][4], aL[2][4];
#pragma unroll
            for (int mt = 0; mt < 2; mt++) {
                int r = wm * 32 + mt * 16 + rl;
                uint32_t base = Ab + (uint32_t)r * 128;
                int cH = 2 * g + kc;
                LDSM_X4(aH[mt], base + (uint32_t)((cH ^ (r & 7)) << 4));
                if (NT == 3)
                    LDSM_X4(aL[mt], base + (uint32_t)(((cH + 4) ^ (r & 7)) << 4));
            }
            uint32_t bH[4][2], bL[4][2];
#pragma unroll
            for (int t = 0; t < 2; t++) {
                int r = wn * 32 + t * 16 + rl;
                uint32_t base = Bb + (uint32_t)r * 128;
                int cH = 2 * g + kc;
                uint32_t q[4];
                LDSM_X4(q, base + (uint32_t)((cH ^ (r & 7)) << 4));
                bH[2*t][0] = q[0]; bH[2*t+1][0] = q[1]; bH[2*t][1] = q[2]; bH[2*t+1][1] = q[3];
                LDSM_X4(q, base + (uint32_t)(((cH + 4) ^ (r & 7)) << 4));
                bL[2*t][0] = q[0]; bL[2*t+1][0] = q[1]; bL[2*t][1] = q[2]; bL[2*t+1][1] = q[3];
            }
#pragma unroll
            for (int mt = 0; mt < 2; mt++)
#pragma unroll
                for (int nt = 0; nt < 4; nt++) {
                    MMA_F16(acc[mt][nt], aH[mt], bH[nt]);
                    MMA_F16(acc[mt][nt], aH[mt], bL[nt]);
                    if (NT == 3) MMA_F16(acc[mt][nt], aL[mt], bH[nt]);
                }
        }
        if (s + 1 < NS) STA((s + 1) & 1);
        CP_WAIT0();
        __syncthreads();
    }

    // ---- epilogue
#pragma unroll
    for (int mt = 0; mt < 2; mt++) {
        int mb = m0 + wm * 32 + mt * 16 + (lane >> 2);
#pragma unroll
        for (int nt = 0; nt < 4; nt++) {
            int ocb = n0 + wn * 32 + nt * 8 + ((lane & 3) << 1);
#pragma unroll
            for (int h = 0; h < 2; h++) {
                int m = mb + h * 8;
#pragma unroll
                for (int q = 0; q < 2; q++) {
                    int oc = ocb + q;
                    float v = acc[mt][nt][h * 2 + q] * SINV + __ldg(bias + oc);
                    size_t ob;
                    if (G == 4) {
                        int y = m >> 5, x = m & 31;
                        ob = ((size_t)(b * Cout + oc)) * 4096 + (size_t)(2*y + ry) * 64 + (2*x + rx);
                    } else {
                        ob = ((size_t)b * Cout + oc) * MIMG + m;
                    }
                    if (ADDRES) v += res[ob];
                    if (ROUT) v = fmaxf(v, 0.f);
                    if (OUTF) outF[ob] = v;
                    if (OUTS) {
                        int y = m >> OWB, x = m & ((1 << OWB) - 1);
                        size_t obS = ((size_t)(b * Cout + oc)) * PS + (size_t)(y + 1) * PW + x + 1;
                        outS[obS] = splitpack(fmaxf(v, 0.f) * SAN);
                    }
                }
            }
        }
    }
}

// ================= fp32 1x1 conv (toz / fz) =================
#define FMA16S \
    acc[0][0] += bv.x*a.x; acc[0][1] += bv.x*a.y; acc[0][2] += bv.x*a.z; acc[0][3] += bv.x*a.w; \
    acc[1][0] += bv.y*a.x; acc[1][1] += bv.y*a.y; acc[1][2] += bv.y*a.z; acc[1][3] += bv.y*a.w; \
    acc[2][0] += bv.z*a.x; acc[2][1] += bv.z*a.y; acc[2][2] += bv.z*a.z; acc[2][3] += bv.z*a.w; \
    acc[3][0] += bv.w*a.x; acc[3][1] += bv.w*a.y; acc[3][2] += bv.w*a.z; acc[3][3] += bv.w*a.w;

template<int ROUT, int OUTS>
__global__ __launch_bounds__(256) void conv1x1_k(
    const float* __restrict__ in, const float* __restrict__ wT,
    const float* __restrict__ bias,
    float* __restrict__ out, uint32_t* __restrict__ outS,
    int Cin, int Cout, float SAN)
{
    const int K = Cin;
    const int b  = blockIdx.z;
    const int m0 = blockIdx.x * 64;
    const int n0 = blockIdx.y * 64;
    __shared__ float As[16][64];
    __shared__ float Bs[16][64];
    const int tid = threadIdx.x;
    const int lm = tid & 63, lk = tid >> 6;
    const int mi = (tid & 15) << 2, ni = (tid >> 4) << 2;
    const float* inb = in + (size_t)b * Cin * 1024;

    float acc[4][4] = {};
    for (int k0 = 0; k0 < K; k0 += 16) {
#pragma unroll
        for (int i = 0; i < 4; i++) {
            int k = k0 + lk + i * 4;
            As[lk + i * 4][lm] = inb[(size_t)k * 1024 + m0 + lm];
            Bs[lk + i * 4][lm] = wT[(size_t)k * Cout + n0 + lm];
        }
        __syncthreads();
#pragma unroll
        for (int kk = 0; kk < 16; kk++) {
            float4 a  = *(const float4*)&As[kk][mi];
            float4 bv = *(const float4*)&Bs[kk][ni];
            FMA16S
        }
        __syncthreads();
    }
    const int m = m0 + mi;
#pragma unroll
    for (int i = 0; i < 4; i++) {
        int oc = n0 + ni + i;
        size_t ob = ((size_t)b * Cout + oc) * 1024 + m;
        float bb = bias[oc];
        float4 r;
        r.x = acc[i][0] + bb; r.y = acc[i][1] + bb;
        r.z = acc[i][2] + bb; r.w = acc[i][3] + bb;
        if (ROUT) {
            r.x = fmaxf(r.x, 0.f); r.y = fmaxf(r.y, 0.f);
            r.z = fmaxf(r.z, 0.f); r.w = fmaxf(r.w, 0.f);
        }
        if (OUTS) {
            int y = m >> 5, x = m & 31;
            size_t base = ((size_t)b * Cout + oc) * 1156 + (size_t)(y + 1) * 34 + x + 1;
            outS[base + 0] = splitpack(fmaxf(r.x, 0.f) * SAN);
            outS[base + 1] = splitpack(fmaxf(r.y, 0.f) * SAN);
            outS[base + 2] = splitpack(fmaxf(r.z, 0.f) * SAN);
            outS[base + 3] = splitpack(fmaxf(r.w, 0.f) * SAN);
        } else {
            *(float4*)&out[ob] = r;
        }
    }
}

// ================= t2 (256 -> 3, 64x64 -> 128x128) + sigmoid =================
__global__ __launch_bounds__(128) void t2_k(const float* __restrict__ w,
                                            const float* __restrict__ bias,
                                            float* __restrict__ out)
{
    const int cls = blockIdx.z, b = blockIdx.y;
    const int ry = cls >> 1, rx = cls & 1;
    const int oy0 = ry ? 1 : 0, oy1 = ry ? 0 : -1;
    const int ox1 = rx ? 0 : -1;
    __shared__ float ws[3072];
    for (int i = threadIdx.x; i < 3072; i += 128) {
        int ic = i / 12, r = i - ic * 12;
        int t = r / 3, oc = r - t * 3;
        int a = t >> 1, bb = t & 1;
        int ky = ry ? (a ? 2 : 0) : (a ? 3 : 1);
        int kx = rx ? (bb ? 2 : 0) : (bb ? 3 : 1);
        ws[i] = w[((size_t)(ic * 3 + oc)) * 16 + ky * 4 + kx];
    }
    __syncthreads();
    const int t = blockIdx.x * 128 + threadIdx.x;
    const int yy = t >> 4;
    const int xg = (t & 15) << 2;
    const int basex = xg + ox1;
    const float* inb = g_d1 + (size_t)b * 256 * 4096;
    float acc[4][3] = {};
    for (int ic = 0; ic < 256; ic++) {
        const float* ip = inb + ic * 4096;
        float v[2][5];
#pragma unroll
        for (int a = 0; a < 2; a++) {
            int iy = yy + (a ? oy1 : oy0);
            bool okr = (unsigned)iy < 64u;
#pragma unroll
            for (int q = 0; q < 5; q++) {
                int ix = basex + q;
                v[a][q] = (okr && (unsigned)ix < 64u) ? ip[iy * 64 + ix] : 0.f;
            }
        }
        const float* wr = &ws[ic * 12];
#pragma unroll
        for (int p = 0; p < 4; p++)
#pragma unroll
            for (int bb2 = 0; bb2 < 2; bb2++) {
#pragma unroll
                for (int a = 0; a < 2; a++) {
                    float val = v[a][p + (bb2 ? 0 : 1)];
                    int ti = a * 2 + bb2;
                    acc[p][0] += val * wr[ti * 3 + 0];
                    acc[p][1] += val * wr[ti * 3 + 1];
                    acc[p][2] += val * wr[ti * 3 + 2];
                }
            }
    }
#pragma unroll
    for (int p = 0; p < 4; p++) {
        int oy = 2 * yy + ry, ox = 2 * (xg + p) + rx;
#pragma unroll
        for (int oc = 0; oc < 3; oc++) {
            float vv = acc[p][oc] + bias[oc];
            out[((size_t)(b * 3 + oc) * 128 + oy) * 128 + ox] = 1.f / (1.f + __expf(-vv));
        }
    }
}

// ================= VQ (chunked argmin) =================
__global__ __launch_bounds__(256) void vq_part(const float* __restrict__ cb)
{
    const int n = blockIdx.x * 256 + threadIdx.x;
    const int chunk = blockIdx.y;
    const int c0base = chunk * 128;
    const int b = n >> 10, s = n & 1023;
    const float* zp = g_ze + (size_t)b * 64 * 1024 + s;
    float z[64];
#pragma unroll
    for (int c = 0; c < 64; c++) z[c] = zp[(size_t)c * 1024];
    float z0 = 0, z1 = 0, z2a = 0, z3 = 0;
#pragma unroll
    for (int c = 0; c < 64; c += 4) {
        z0 += z[c]*z[c]; z1 += z[c+1]*z[c+1]; z2a += z[c+2]*z[c+2]; z3 += z[c+3]*z[c+3];
    }
    const float zn = (z0 + z1) + (z2a + z3);
    __shared__ float cbs[8192];
    for (int i = threadIdx.x; i < 8192; i += 256)
        cbs[i] = cb[(size_t)c0base * 64 + i];
    __syncthreads();
    float best = 3.4e38f; int bid = 0;
    for (int k = 0; k < 128; k++) {
        const float* cr = &cbs[k * 64];
        float d0 = 0, d1 = 0, d2 = 0, d3 = 0;
#pragma unroll
        for (int c = 0; c < 64; c += 4) {
            d0 += z[c]*cr[c]; d1 += z[c+1]*cr[c+1]; d2 += z[c+2]*cr[c+2]; d3 += z[c+3]*cr[c+3];
        }
        float dot = (d0 + d1) + (d2 + d3);
        float score = (zn - 2.0f * dot) + g_cbn[c0base + k];
        if (score < best) { best = score; bid = c0base + k; }
    }
    g_vqs[chunk * 8192 + n] = best;
    g_vqi[chunk * 8192 + n] = bid;
}
__global__ __launch_bounds__(256) void vq_reduce(const float* __restrict__ cb)
{
    const int n = blockIdx.x * 256 + threadIdx.x;
    float best = g_vqs[n]; int bid = g_vqi[n];
#pragma unroll
    for (int ch = 1; ch < 4; ch++) {
        float s = g_vqs[ch * 8192 + n];
        int   i = g_vqi[ch * 8192 + n];
        if (s < best) { best = s; bid = i; }
    }
    g_ids[n] = bid;
    const int b = n >> 10, s2 = n & 1023;
    const float* code = cb + (size_t)bid * 64;
    float* ep = g_ek + (size_t)b * 64 * 1024 + s2;
#pragma unroll
    for (int c = 0; c < 64; c++) ep[(size_t)c * 1024] = code[c];
}

// ================= pack tuple tail =================
__global__ void pack_k(float* __restrict__ out, int out_size)
{
    int i = blockIdx.x * 256 + threadIdx.x;
    if (i < 524288) {
        int o = 393216 + i;
        if (o < out_size) out[o] = g_ze[i];
    } else if (i < 1048576) {
        int j = i - 524288;
        int o = 917504 + j;
        if (o < out_size) out[o] = g_ek[j];
    } else if (i < 1056768) {
        int j = i - 1048576;
        int o = 1441792 + j;
        if (o < out_size) out[o] = (float)g_ids[j];
    }
}

// ================= launch =================
static constexpr int SMEM_TC = 2 * 24576 + 256;

extern "C" void kernel_launch(void* const* d_in, const int* in_sizes, int n_in,
                              void* d_out, int out_size)
{
    const float* x     = (const float*)d_in[0];
    const float* c1_w  = (const float*)d_in[1];
    const float* c1_b  = (const float*)d_in[2];
    const float* c2_w  = (const float*)d_in[3];
    const float* c2_b  = (const float*)d_in[4];
    const float* r0_w3 = (const float*)d_in[5];
    const float* r0_b3 = (const float*)d_in[6];
    const float* r0_w1 = (const float*)d_in[7];
    const float* r0_b1 = (const float*)d_in[8];
    const float* r1_w3 = (const float*)d_in[9];
    const float* r1_b3 = (const float*)d_in[10];
    const float* r1_w1 = (const float*)d_in[11];
    const float* r1_b1 = (const float*)d_in[12];
    const float* toz_w = (const float*)d_in[13];
    const float* toz_b = (const float*)d_in[14];
    const float* cb    = (const float*)d_in[15];
    const float* fz_w  = (const float*)d_in[16];
    const float* fz_b  = (const float*)d_in[17];
    const float* t1_w  = (const float*)d_in[18];
    const float* t1_b  = (const float*)d_in[19];
    const float* t2_w  = (const float*)d_in[20];
    const float* t2_b  = (const float*)d_in[21];
    float* out = (float*)d_out;

    void* p;
#define GETF(var, sym) cudaGetSymbolAddress(&p, sym); float* var = (float*)p;
#define GETU(var, sym) cudaGetSymbolAddress(&p, sym); uint32_t* var = (uint32_t*)p;
    GETF(h2p,  g_h2)   GETF(zep,  g_ze)   GETF(ekp,  g_ek)   GETF(d1p,  g_d1)
    GETF(wtoz, g_wtoz) GETF(wfz,  g_wfz)
    GETU(xs,   g_xs)   GETU(h1s,  g_h1s)  GETU(acts, g_acts) GETU(rs,   g_rs)
    GETU(d0s,  g_d0s)
    GETU(wc1s, g_wc1s) GETU(wc2s, g_wc2s) GETU(wr03s,g_wr03s) GETU(wr01s,g_wr01s)
    GETU(wr13s,g_wr13s) GETU(wr11s,g_wr11s) GETU(wt1s, g_wt1s)
#undef GETF
#undef GETU

    // tconv instantiations  <G,NT,OUTF,OUTS,ADDRES,ROUT,OWB,MIMG,PS,PW>
    auto* kc1  = tconv<0, 3, 0, 1, 0, 1, 6, 4096, 4489, 67>;
    auto* kc2  = tconv<1, 3, 1, 1, 0, 1, 5, 1024, 1156, 34>;
    auto* kr3  = tconv<2, 3, 0, 1, 0, 0, 5, 1024, 1156, 34>;
    auto* kr1a = tconv<3, 3, 1, 1, 1, 0, 5, 1024, 1156, 34>;
    auto* kr1b = tconv<3, 3, 1, 0, 1, 0, 5, 1024, 1156, 34>;
    auto* kt1  = tconv<4, 2, 1, 0, 0, 1, 5, 1024, 1156, 34>;
    cudaFuncSetAttribute(kc1,  cudaFuncAttributeMaxDynamicSharedMemorySize, SMEM_TC);
    cudaFuncSetAttribute(kc2,  cudaFuncAttributeMaxDynamicSharedMemorySize, SMEM_TC);
    cudaFuncSetAttribute(kr3,  cudaFuncAttributeMaxDynamicSharedMemorySize, SMEM_TC);
    cudaFuncSetAttribute(kr1a, cudaFuncAttributeMaxDynamicSharedMemorySize, SMEM_TC);
    cudaFuncSetAttribute(kr1b, cudaFuncAttributeMaxDynamicSharedMemorySize, SMEM_TC);
    cudaFuncSetAttribute(kt1,  cudaFuncAttributeMaxDynamicSharedMemorySize, SMEM_TC);

    const float SA = 256.f, SW = 1024.f;
    const float SI  = 1.f / (256.f * 1024.f);
    const float SAT = 16384.f, SIT = 1.f / (16384.f * 1024.f);

    const int HZT = 24*777 + 17168 + 2048*393 + 3*2048*132;
    const int PET = 8*3*16384 + 256*64 + 256*4096;

    // launch order: kernel index 3 (0-based) == kc2, the profiled slot
    halo_zero<<<(HZT + 255) / 256, 256>>>();                             // 0
    prep_enc<<<(PET + 255) / 256, 256>>>(x, c1_w, c2_w, SA, SW);         // 1
    kc1<<<dim3(64,2,8), 256, SMEM_TC>>>(xs, wc1s, c1_b, nullptr,         // 2
        nullptr, h1s, 64, 256, SI, SA);
    kc2<<<dim3(16,2,8), 256, SMEM_TC>>>(h1s, wc2s, c2_b, nullptr,        // 3 <- profiled
        h2p, acts, 4096, 256, SI, SA);

    wsplit<<<(256*2304) / 256, 256>>>(r0_w3, wr03s, 2304, 2304, SW);
    kr3 <<<dim3(16,2,8), 256, SMEM_TC>>>(acts, wr03s, r0_b3, nullptr, nullptr, rs, 2304, 256, SI, SA);
    wsplit<<<(256*256)  / 256, 256>>>(r0_w1, wr01s, 256, 256, SW);
    kr1a<<<dim3(16,2,8), 256, SMEM_TC>>>(rs,   wr01s, r0_b1, h2p,     h2p, acts, 256,  256, SI, SA);
    wsplit<<<(256*2304) / 256, 256>>>(r1_w3, wr13s, 2304, 2304, SW);
    kr3 <<<dim3(16,2,8), 256, SMEM_TC>>>(acts, wr13s, r1_b3, nullptr, nullptr, rs, 2304, 256, SI, SA);
    wsplit<<<(256*256)  / 256, 256>>>(r1_w1, wr11s, 256, 256, SW);
    kr1b<<<dim3(16,2,8), 256, SMEM_TC>>>(rs,   wr11s, r1_b1, h2p,     h2p, nullptr, 256, 256, SI, 0.f);

    wtrans<<<(256*64) / 256, 256>>>(toz_w, wtoz, 64, 256);
    conv1x1_k<0,0><<<dim3(16,1,8), 256>>>(h2p, wtoz, toz_b, zep, nullptr, 256, 64, 0.f);

    // vector quantization
    cbnorm_k<<<8, 64>>>(cb);
    vq_part<<<dim3(32,4), 256>>>(cb);
    vq_reduce<<<32, 256>>>(cb);

    // decoder
    wtrans<<<(64*256) / 256, 256>>>(fz_w, wfz, 256, 64);
    conv1x1_k<1,1><<<dim3(16,4,8), 256>>>(ekp, wfz, fz_b, nullptr, d0s, 64, 256, SAT);
    wt1split<<<(4*256*1024) / 256, 256>>>(t1_w, wt1s, SW);
    kt1<<<dim3(16,2,32), 256, SMEM_TC>>>(d0s, wt1s, t1_b, nullptr, d1p, nullptr, 1024, 256, SIT, 0.f);
    t2_k<<<dim3(8,8,4), 128>>>(t2_w, t2_b, out);

    // pack z_e / e_k / ids
    pack_k<<<4128, 256>>>(out, out_size);
}